// round 5
// baseline (speedup 1.0000x reference)
#include <cuda_runtime.h>
#include <math.h>

#define B_    2
#define QLEN  2048
#define HID   2048
#define HQ    16
#define HKV   4
#define DH    128
#define QKVN  (HQ*DH + 2*HKV*DH)   /* 3072 */
#define NTOK  (B_*QLEN)            /* 4096 */

// ---------------- scratch (device globals: allocation-free) ----------------
__device__ float g_qkv [NTOK * QKVN];            // 50.3 MB
__device__ float g_q   [B_ * HQ  * QLEN * DH];   // 33.5 MB
__device__ float g_k   [B_ * HKV * QLEN * DH];   //  8.4 MB
__device__ float g_v   [B_ * HKV * QLEN * DH];   //  8.4 MB
__device__ float g_attn[NTOK * HQ * DH];         // 33.5 MB

// ---------------- SGEMM: C[M,N] = A[M,K] * B[N,K]^T (both row-major) -------
// 128x128 tile, BK=8, 256 threads, 8x8 per thread.
__global__ __launch_bounds__(256) void sgemm_nt(
    const float* __restrict__ A, const float* __restrict__ Bm,
    float* __restrict__ C, int M, int N, int K)
{
    __shared__ float As[8][128];
    __shared__ float Bs[8][128];
    int tid = threadIdx.x;
    int bm = blockIdx.y * 128;
    int bn = blockIdx.x * 128;
    int lr = tid >> 1;            // 0..127
    int lc = (tid & 1) * 4;       // 0 or 4
    const float* Ap = A  + (size_t)(bm + lr) * K + lc;
    const float* Bp = Bm + (size_t)(bn + lr) * K + lc;
    int ty = tid >> 4, tx = tid & 15;
    float acc[8][8];
    #pragma unroll
    for (int i = 0; i < 8; i++)
        #pragma unroll
        for (int j = 0; j < 8; j++) acc[i][j] = 0.f;

    for (int kt = 0; kt < K; kt += 8) {
        float4 av = *(const float4*)(Ap + kt);
        float4 bv = *(const float4*)(Bp + kt);
        As[lc+0][lr] = av.x; As[lc+1][lr] = av.y; As[lc+2][lr] = av.z; As[lc+3][lr] = av.w;
        Bs[lc+0][lr] = bv.x; Bs[lc+1][lr] = bv.y; Bs[lc+2][lr] = bv.z; Bs[lc+3][lr] = bv.w;
        __syncthreads();
        #pragma unroll
        for (int k = 0; k < 8; k++) {
            float4 a0 = *(const float4*)&As[k][ty*8];
            float4 a1 = *(const float4*)&As[k][ty*8+4];
            float4 b0 = *(const float4*)&Bs[k][tx*8];
            float4 b1 = *(const float4*)&Bs[k][tx*8+4];
            float ar[8] = {a0.x,a0.y,a0.z,a0.w,a1.x,a1.y,a1.z,a1.w};
            float br[8] = {b0.x,b0.y,b0.z,b0.w,b1.x,b1.y,b1.z,b1.w};
            #pragma unroll
            for (int i = 0; i < 8; i++)
                #pragma unroll
                for (int j = 0; j < 8; j++)
                    acc[i][j] = fmaf(ar[i], br[j], acc[i][j]);
        }
        __syncthreads();
    }
    #pragma unroll
    for (int i = 0; i < 8; i++) {
        float* crow = C + (size_t)(bm + ty*8 + i) * N + bn + tx*8;
        float4 v0; v0.x = acc[i][0]; v0.y = acc[i][1]; v0.z = acc[i][2]; v0.w = acc[i][3];
        float4 v1; v1.x = acc[i][4]; v1.y = acc[i][5]; v1.z = acc[i][6]; v1.w = acc[i][7];
        *(float4*)crow       = v0;
        *(float4*)(crow + 4) = v1;
    }
}

// ---------------- fused RMSNorm + RoPE + scatter to q/k/v ------------------
// grid (NTOK, 24): heads 0..15 = q, 16..19 = k, 20..23 = v. block = 128 (=DH)
__global__ __launch_bounds__(128) void rmsnorm_rope(
    const int* __restrict__ pos,
    const float* __restrict__ qw, const float* __restrict__ kw)
{
    int token = blockIdx.x;
    int h = blockIdx.y;
    int d = threadIdx.x;
    int b = token / QLEN, q = token % QLEN;

    if (h >= 20) {  // V: straight copy (entire block uniform)
        int hv = h - 20;
        g_v[(((size_t)b*HKV + hv)*QLEN + q)*DH + d] =
            g_qkv[(size_t)token*QKVN + HQ*DH + HKV*DH + hv*DH + d];
        return;
    }
    bool isq = (h < 16);
    int off = isq ? h*DH : HQ*DH + (h-16)*DH;
    float x = g_qkv[(size_t)token*QKVN + off + d];

    __shared__ float red[4];
    __shared__ float sx[128];
    float s = x * x;
    #pragma unroll
    for (int o = 16; o; o >>= 1) s += __shfl_xor_sync(0xffffffffu, s, o);
    if ((d & 31) == 0) red[d >> 5] = s;
    __syncthreads();
    float tot = red[0] + red[1] + red[2] + red[3];
    float r = rsqrtf(tot * (1.0f/DH) + 1e-6f);
    const float* w = isq ? qw : kw;
    float xn = x * r * w[d];
    sx[d] = xn;
    __syncthreads();

    float p = (float)pos[token];
    int i = d & 63;
    float invf = exp2f(-((float)i) * (log2f(1.0e6f) / 64.0f));
    float ang = p * invf;
    float c = cosf(ang), sn = sinf(ang);
    float outv = (d < 64) ? (sx[d]*c - sx[d+64]*sn)
                          : (sx[d]*c + sx[d-64]*sn);
    if (isq) g_q[(((size_t)b*HQ  + h     )*QLEN + q)*DH + d] = outv;
    else     g_k[(((size_t)b*HKV + (h-16))*QLEN + q)*DH + d] = outv;
}

// ---------------- flash attention (fp32, causal, GQA) ----------------------
#define FBM 64
#define FBN 64
#define SD  132   // padded row stride to break bank conflicts
#define FLASH_SMEM ((3*FBM*SD + FBM*65 + 3*FBM) * 4)

__global__ __launch_bounds__(256) void flash_attn()
{
    extern __shared__ float sm_[];
    float* sQ  = sm_;
    float* sK  = sQ + FBM*SD;
    float* sV  = sK + FBN*SD;
    float* sS  = sV + FBN*SD;       // FBM x 65
    float* sMx = sS + FBM*65;
    float* sL  = sMx + FBM;
    float* sA  = sL + FBM;

    int tid = threadIdx.x;
    int qt = blockIdx.x, h = blockIdx.y, b = blockIdx.z;
    int hkv = h >> 2;   // rep = 4

    const float* Qg = g_q + (((size_t)b*HQ  + h  )*QLEN + qt*FBM)*DH;
    const float* Kg = g_k + (((size_t)b*HKV + hkv)*QLEN)*DH;
    const float* Vg = g_v + (((size_t)b*HKV + hkv)*QLEN)*DH;

    #pragma unroll
    for (int it = 0; it < 8; it++) {
        int e = tid + it*256;
        int row = e >> 5, c4 = (e & 31) << 2;
        *(float4*)&sQ[row*SD + c4] = *(const float4*)&Qg[row*DH + c4];
    }
    if (tid < FBM) { sMx[tid] = -1e30f; sL[tid] = 0.f; }

    float o[8][4];
    #pragma unroll
    for (int i = 0; i < 8; i++)
        #pragma unroll
        for (int j = 0; j < 4; j++) o[i][j] = 0.f;

    int rg = tid >> 5;            // row group: 8 rows each
    int cg = (tid & 31) << 2;     // col base: 4 cols
    const float scale = 0.08838834764831845f;  // 1/sqrt(128)
    int ty = tid >> 4, tx = tid & 15;

    for (int kb = 0; kb <= qt; kb++) {
        __syncthreads();   // K/V smem reuse barrier (also covers Q-load on kb=0)
        #pragma unroll
        for (int it = 0; it < 8; it++) {
            int e = tid + it*256;
            int row = e >> 5, c4 = (e & 31) << 2;
            *(float4*)&sK[row*SD + c4] = *(const float4*)&Kg[((size_t)kb*FBN + row)*DH + c4];
            *(float4*)&sV[row*SD + c4] = *(const float4*)&Vg[((size_t)kb*FBN + row)*DH + c4];
        }
        __syncthreads();

        // S = Q K^T : thread computes 4x4 tile
        float acc[4][4];
        #pragma unroll
        for (int a = 0; a < 4; a++)
            #pragma unroll
            for (int c = 0; c < 4; c++) acc[a][c] = 0.f;
        #pragma unroll 4
        for (int k = 0; k < DH; k += 4) {
            float4 qv[4], kv[4];
            #pragma unroll
            for (int a = 0; a < 4; a++) qv[a] = *(const float4*)&sQ[(ty*4+a)*SD + k];
            #pragma unroll
            for (int c = 0; c < 4; c++) kv[c] = *(const float4*)&sK[(tx*4+c)*SD + k];
            #pragma unroll
            for (int a = 0; a < 4; a++)
                #pragma unroll
                for (int c = 0; c < 4; c++)
                    acc[a][c] += qv[a].x*kv[c].x + qv[a].y*kv[c].y
                               + qv[a].z*kv[c].z + qv[a].w*kv[c].w;
        }
        #pragma unroll
        for (int a = 0; a < 4; a++) {
            int grow = qt*FBM + ty*4 + a;
            #pragma unroll
            for (int c = 0; c < 4; c++) {
                int gcol = kb*FBN + tx*4 + c;
                sS[(ty*4+a)*65 + tx*4+c] = (gcol <= grow) ? acc[a][c]*scale : -1e30f;
            }
        }
        __syncthreads();

        // online softmax, one thread per row
        if (tid < FBM) {
            int i = tid;
            float m = sMx[i], mn = m;
            #pragma unroll 8
            for (int j = 0; j < FBN; j++) mn = fmaxf(mn, sS[i*65+j]);
            float al = __expf(m - mn);
            float sum = 0.f;
            #pragma unroll 8
            for (int j = 0; j < FBN; j++) {
                float pij = __expf(sS[i*65+j] - mn);
                sS[i*65+j] = pij;
                sum += pij;
            }
            sL[i] = sL[i]*al + sum;
            sMx[i] = mn;
            sA[i] = al;
        }
        __syncthreads();

        // O = O*alpha + P*V
        #pragma unroll
        for (int i = 0; i < 8; i++) {
            float al = sA[rg*8 + i];
            #pragma unroll
            for (int c = 0; c < 4; c++) o[i][c] *= al;
        }
        #pragma unroll 4
        for (int j = 0; j < FBN; j++) {
            float4 v4 = *(const float4*)&sV[j*SD + cg];
            #pragma unroll
            for (int i = 0; i < 8; i++) {
                float p = sS[(rg*8+i)*65 + j];
                o[i][0] = fmaf(p, v4.x, o[i][0]);
                o[i][1] = fmaf(p, v4.y, o[i][1]);
                o[i][2] = fmaf(p, v4.z, o[i][2]);
                o[i][3] = fmaf(p, v4.w, o[i][3]);
            }
        }
    }
    __syncthreads();

    #pragma unroll
    for (int i = 0; i < 8; i++) {
        int row = rg*8 + i;
        float inv = 1.0f / sL[row];
        int q = qt*FBM + row;
        float4 v;
        v.x = o[i][0]*inv; v.y = o[i][1]*inv; v.z = o[i][2]*inv; v.w = o[i][3]*inv;
        *(float4*)&g_attn[((size_t)(b*QLEN + q))*(HQ*DH) + h*DH + cg] = v;
    }
}

// ---------------------------------------------------------------------------
extern "C" void kernel_launch(void* const* d_in, const int* in_sizes, int n_in,
                              void* d_out, int out_size)
{
    const int*   positions = (const int*)  d_in[0];
    const float* hidden    = (const float*)d_in[1];
    // d_in[2]=k_cache, d_in[3]=v_cache: zeros with start=0 -> fully overwritten, unused
    const float* wqkv      = (const float*)d_in[4];
    const float* wo        = (const float*)d_in[5];
    const float* qw        = (const float*)d_in[6];
    const float* kw        = (const float*)d_in[7];
    float* out = (float*)d_out;

    float *p_qkv, *p_attn;
    cudaGetSymbolAddress((void**)&p_qkv,  g_qkv);
    cudaGetSymbolAddress((void**)&p_attn, g_attn);

    // 1) QKV projection: [4096,3072] = hidden[4096,2048] @ wqkv^T
    sgemm_nt<<<dim3(QKVN/128, NTOK/128), 256>>>(hidden, wqkv, p_qkv, NTOK, QKVN, HID);

    // 2) RMSNorm + RoPE + scatter
    rmsnorm_rope<<<dim3(NTOK, 24), 128>>>(positions, qw, kw);

    // 3) causal GQA flash attention
    cudaFuncSetAttribute(flash_attn, cudaFuncAttributeMaxDynamicSharedMemorySize, FLASH_SMEM);
    flash_attn<<<dim3(QLEN/FBM, HQ, B_), 256, FLASH_SMEM>>>();

    // 4) output projection: [4096,2048] = attn[4096,2048] @ wo^T
    sgemm_nt<<<dim3(HID/128, NTOK/128), 256>>>(p_attn, wo, out, NTOK, HID, HID);
}

// round 6
// speedup vs baseline: 1.0004x; 1.0004x over previous
#include <cuda_runtime.h>
#include <math.h>

#define B_    2
#define QLEN  2048
#define HID   2048
#define HQ    16
#define HKV   4
#define DH    128
#define QKVN  (HQ*DH + 2*HKV*DH)   /* 3072 */
#define NTOK  (B_*QLEN)            /* 4096 */

// ---------------- scratch (device globals: allocation-free) ----------------
__device__ float g_qkv [NTOK * QKVN];            // 50.3 MB
__device__ float g_q   [B_ * HQ  * QLEN * DH];   // 33.5 MB
__device__ float g_k   [B_ * HKV * QLEN * DH];   //  8.4 MB
__device__ float g_v   [B_ * HKV * QLEN * DH];   //  8.4 MB
__device__ float g_attn[NTOK * HQ * DH];         // 33.5 MB

// ---------------- SGEMM: C[M,N] = A[M,K] * B[N,K]^T (both row-major) -------
// 128x128 tile, BK=8, 256 threads, 8x8 per thread.
__global__ __launch_bounds__(256) void sgemm_nt(
    const float* __restrict__ A, const float* __restrict__ Bm,
    float* __restrict__ C, int M, int N, int K)
{
    __shared__ float As[8][128];
    __shared__ float Bs[8][128];
    int tid = threadIdx.x;
    int bm = blockIdx.y * 128;
    int bn = blockIdx.x * 128;
    int lr = tid >> 1;            // 0..127
    int lc = (tid & 1) * 4;       // 0 or 4
    const float* Ap = A  + (size_t)(bm + lr) * K + lc;
    const float* Bp = Bm + (size_t)(bn + lr) * K + lc;
    int ty = tid >> 4, tx = tid & 15;
    float acc[8][8];
    #pragma unroll
    for (int i = 0; i < 8; i++)
        #pragma unroll
        for (int j = 0; j < 8; j++) acc[i][j] = 0.f;

    for (int kt = 0; kt < K; kt += 8) {
        float4 av = *(const float4*)(Ap + kt);
        float4 bv = *(const float4*)(Bp + kt);
        As[lc+0][lr] = av.x; As[lc+1][lr] = av.y; As[lc+2][lr] = av.z; As[lc+3][lr] = av.w;
        Bs[lc+0][lr] = bv.x; Bs[lc+1][lr] = bv.y; Bs[lc+2][lr] = bv.z; Bs[lc+3][lr] = bv.w;
        __syncthreads();
        #pragma unroll
        for (int k = 0; k < 8; k++) {
            float4 a0 = *(const float4*)&As[k][ty*8];
            float4 a1 = *(const float4*)&As[k][ty*8+4];
            float4 b0 = *(const float4*)&Bs[k][tx*8];
            float4 b1 = *(const float4*)&Bs[k][tx*8+4];
            float ar[8] = {a0.x,a0.y,a0.z,a0.w,a1.x,a1.y,a1.z,a1.w};
            float br[8] = {b0.x,b0.y,b0.z,b0.w,b1.x,b1.y,b1.z,b1.w};
            #pragma unroll
            for (int i = 0; i < 8; i++)
                #pragma unroll
                for (int j = 0; j < 8; j++)
                    acc[i][j] = fmaf(ar[i], br[j], acc[i][j]);
        }
        __syncthreads();
    }
    #pragma unroll
    for (int i = 0; i < 8; i++) {
        float* crow = C + (size_t)(bm + ty*8 + i) * N + bn + tx*8;
        float4 v0; v0.x = acc[i][0]; v0.y = acc[i][1]; v0.z = acc[i][2]; v0.w = acc[i][3];
        float4 v1; v1.x = acc[i][4]; v1.y = acc[i][5]; v1.z = acc[i][6]; v1.w = acc[i][7];
        *(float4*)crow       = v0;
        *(float4*)(crow + 4) = v1;
    }
}

// ---------------- fused RMSNorm + RoPE + scatter to q/k/v ------------------
// grid (NTOK, 24): heads 0..15 = q, 16..19 = k, 20..23 = v. block = 128 (=DH)
__global__ __launch_bounds__(128) void rmsnorm_rope(
    const int* __restrict__ pos,
    const float* __restrict__ qw, const float* __restrict__ kw)
{
    int token = blockIdx.x;
    int h = blockIdx.y;
    int d = threadIdx.x;
    int b = token / QLEN, q = token % QLEN;

    if (h >= 20) {  // V: straight copy (entire block uniform)
        int hv = h - 20;
        g_v[(((size_t)b*HKV + hv)*QLEN + q)*DH + d] =
            g_qkv[(size_t)token*QKVN + HQ*DH + HKV*DH + hv*DH + d];
        return;
    }
    bool isq = (h < 16);
    int off = isq ? h*DH : HQ*DH + (h-16)*DH;
    float x = g_qkv[(size_t)token*QKVN + off + d];

    __shared__ float red[4];
    __shared__ float sx[128];
    float s = x * x;
    #pragma unroll
    for (int o = 16; o; o >>= 1) s += __shfl_xor_sync(0xffffffffu, s, o);
    if ((d & 31) == 0) red[d >> 5] = s;
    __syncthreads();
    float tot = red[0] + red[1] + red[2] + red[3];
    float r = rsqrtf(tot * (1.0f/DH) + 1e-6f);
    const float* w = isq ? qw : kw;
    float xn = x * r * w[d];
    sx[d] = xn;
    __syncthreads();

    float p = (float)pos[token];
    int i = d & 63;
    float invf = exp2f(-((float)i) * (log2f(1.0e6f) / 64.0f));
    float ang = p * invf;
    float c = cosf(ang), sn = sinf(ang);
    float outv = (d < 64) ? (sx[d]*c - sx[d+64]*sn)
                          : (sx[d]*c + sx[d-64]*sn);
    if (isq) g_q[(((size_t)b*HQ  + h     )*QLEN + q)*DH + d] = outv;
    else     g_k[(((size_t)b*HKV + (h-16))*QLEN + q)*DH + d] = outv;
}

// ---------------- flash attention (fp32, causal, GQA) ----------------------
#define FBM 64
#define FBN 64
#define SD  132   // padded row stride to break bank conflicts
#define FLASH_SMEM ((3*FBM*SD + FBM*65 + 3*FBM) * 4)

__global__ __launch_bounds__(256) void flash_attn()
{
    extern __shared__ float sm_[];
    float* sQ  = sm_;
    float* sK  = sQ + FBM*SD;
    float* sV  = sK + FBN*SD;
    float* sS  = sV + FBN*SD;       // FBM x 65
    float* sMx = sS + FBM*65;
    float* sL  = sMx + FBM;
    float* sA  = sL + FBM;

    int tid = threadIdx.x;
    int qt = blockIdx.x, h = blockIdx.y, b = blockIdx.z;
    int hkv = h >> 2;   // rep = 4

    const float* Qg = g_q + (((size_t)b*HQ  + h  )*QLEN + qt*FBM)*DH;
    const float* Kg = g_k + (((size_t)b*HKV + hkv)*QLEN)*DH;
    const float* Vg = g_v + (((size_t)b*HKV + hkv)*QLEN)*DH;

    #pragma unroll
    for (int it = 0; it < 8; it++) {
        int e = tid + it*256;
        int row = e >> 5, c4 = (e & 31) << 2;
        *(float4*)&sQ[row*SD + c4] = *(const float4*)&Qg[row*DH + c4];
    }
    if (tid < FBM) { sMx[tid] = -1e30f; sL[tid] = 0.f; }

    float o[8][4];
    #pragma unroll
    for (int i = 0; i < 8; i++)
        #pragma unroll
        for (int j = 0; j < 4; j++) o[i][j] = 0.f;

    int rg = tid >> 5;            // row group: 8 rows each
    int cg = (tid & 31) << 2;     // col base: 4 cols
    const float scale = 0.08838834764831845f;  // 1/sqrt(128)
    int ty = tid >> 4, tx = tid & 15;

    for (int kb = 0; kb <= qt; kb++) {
        __syncthreads();   // K/V smem reuse barrier (also covers Q-load on kb=0)
        #pragma unroll
        for (int it = 0; it < 8; it++) {
            int e = tid + it*256;
            int row = e >> 5, c4 = (e & 31) << 2;
            *(float4*)&sK[row*SD + c4] = *(const float4*)&Kg[((size_t)kb*FBN + row)*DH + c4];
            *(float4*)&sV[row*SD + c4] = *(const float4*)&Vg[((size_t)kb*FBN + row)*DH + c4];
        }
        __syncthreads();

        // S = Q K^T : thread computes 4x4 tile
        float acc[4][4];
        #pragma unroll
        for (int a = 0; a < 4; a++)
            #pragma unroll
            for (int c = 0; c < 4; c++) acc[a][c] = 0.f;
        #pragma unroll 4
        for (int k = 0; k < DH; k += 4) {
            float4 qv[4], kv[4];
            #pragma unroll
            for (int a = 0; a < 4; a++) qv[a] = *(const float4*)&sQ[(ty*4+a)*SD + k];
            #pragma unroll
            for (int c = 0; c < 4; c++) kv[c] = *(const float4*)&sK[(tx*4+c)*SD + k];
            #pragma unroll
            for (int a = 0; a < 4; a++)
                #pragma unroll
                for (int c = 0; c < 4; c++)
                    acc[a][c] += qv[a].x*kv[c].x + qv[a].y*kv[c].y
                               + qv[a].z*kv[c].z + qv[a].w*kv[c].w;
        }
        #pragma unroll
        for (int a = 0; a < 4; a++) {
            int grow = qt*FBM + ty*4 + a;
            #pragma unroll
            for (int c = 0; c < 4; c++) {
                int gcol = kb*FBN + tx*4 + c;
                sS[(ty*4+a)*65 + tx*4+c] = (gcol <= grow) ? acc[a][c]*scale : -1e30f;
            }
        }
        __syncthreads();

        // online softmax, one thread per row
        if (tid < FBM) {
            int i = tid;
            float m = sMx[i], mn = m;
            #pragma unroll 8
            for (int j = 0; j < FBN; j++) mn = fmaxf(mn, sS[i*65+j]);
            float al = __expf(m - mn);
            float sum = 0.f;
            #pragma unroll 8
            for (int j = 0; j < FBN; j++) {
                float pij = __expf(sS[i*65+j] - mn);
                sS[i*65+j] = pij;
                sum += pij;
            }
            sL[i] = sL[i]*al + sum;
            sMx[i] = mn;
            sA[i] = al;
        }
        __syncthreads();

        // O = O*alpha + P*V
        #pragma unroll
        for (int i = 0; i < 8; i++) {
            float al = sA[rg*8 + i];
            #pragma unroll
            for (int c = 0; c < 4; c++) o[i][c] *= al;
        }
        #pragma unroll 4
        for (int j = 0; j < FBN; j++) {
            float4 v4 = *(const float4*)&sV[j*SD + cg];
            #pragma unroll
            for (int i = 0; i < 8; i++) {
                float p = sS[(rg*8+i)*65 + j];
                o[i][0] = fmaf(p, v4.x, o[i][0]);
                o[i][1] = fmaf(p, v4.y, o[i][1]);
                o[i][2] = fmaf(p, v4.z, o[i][2]);
                o[i][3] = fmaf(p, v4.w, o[i][3]);
            }
        }
    }
    __syncthreads();

    #pragma unroll
    for (int i = 0; i < 8; i++) {
        int row = rg*8 + i;
        float inv = 1.0f / sL[row];
        int q = qt*FBM + row;
        float4 v;
        v.x = o[i][0]*inv; v.y = o[i][1]*inv; v.z = o[i][2]*inv; v.w = o[i][3]*inv;
        *(float4*)&g_attn[((size_t)(b*QLEN + q))*(HQ*DH) + h*DH + cg] = v;
    }
}

// ---------------------------------------------------------------------------
extern "C" void kernel_launch(void* const* d_in, const int* in_sizes, int n_in,
                              void* d_out, int out_size)
{
    const int*   positions = (const int*)  d_in[0];
    const float* hidden    = (const float*)d_in[1];
    // d_in[2]=k_cache, d_in[3]=v_cache: zeros with start=0 -> fully overwritten, unused
    const float* wqkv      = (const float*)d_in[4];
    const float* wo        = (const float*)d_in[5];
    const float* qw        = (const float*)d_in[6];
    const float* kw        = (const float*)d_in[7];
    float* out = (float*)d_out;

    float *p_qkv, *p_attn;
    cudaGetSymbolAddress((void**)&p_qkv,  g_qkv);
    cudaGetSymbolAddress((void**)&p_attn, g_attn);

    // 1) QKV projection: [4096,3072] = hidden[4096,2048] @ wqkv^T
    sgemm_nt<<<dim3(QKVN/128, NTOK/128), 256>>>(hidden, wqkv, p_qkv, NTOK, QKVN, HID);

    // 2) RMSNorm + RoPE + scatter
    rmsnorm_rope<<<dim3(NTOK, 24), 128>>>(positions, qw, kw);

    // 3) causal GQA flash attention
    cudaFuncSetAttribute(flash_attn, cudaFuncAttributeMaxDynamicSharedMemorySize, FLASH_SMEM);
    flash_attn<<<dim3(QLEN/FBM, HQ, B_), 256, FLASH_SMEM>>>();

    // 4) output projection: [4096,2048] = attn[4096,2048] @ wo^T
    sgemm_nt<<<dim3(HID/128, NTOK/128), 256>>>(p_attn, wo, out, NTOK, HID, HID);
}

// round 7
// speedup vs baseline: 1.0005x; 1.0001x over previous
#include <cuda_runtime.h>
#include <math.h>

#define B_    2
#define QLEN  2048
#define HID   2048
#define HQ    16
#define HKV   4
#define DH    128
#define QKVN  (HQ*DH + 2*HKV*DH)   /* 3072 */
#define NTOK  (B_*QLEN)            /* 4096 */

// ---------------- scratch (device globals: allocation-free) ----------------
__device__ float g_qkv [NTOK * QKVN];            // 50.3 MB
__device__ float g_q   [B_ * HQ  * QLEN * DH];   // 33.5 MB
__device__ float g_k   [B_ * HKV * QLEN * DH];   //  8.4 MB
__device__ float g_v   [B_ * HKV * QLEN * DH];   //  8.4 MB
__device__ float g_attn[NTOK * HQ * DH];         // 33.5 MB

// ---------------- SGEMM: C[M,N] = A[M,K] * B[N,K]^T (both row-major) -------
// 128x128 tile, BK=8, 256 threads, 8x8 per thread.
__global__ __launch_bounds__(256) void sgemm_nt(
    const float* __restrict__ A, const float* __restrict__ Bm,
    float* __restrict__ C, int M, int N, int K)
{
    __shared__ float As[8][128];
    __shared__ float Bs[8][128];
    int tid = threadIdx.x;
    int bm = blockIdx.y * 128;
    int bn = blockIdx.x * 128;
    int lr = tid >> 1;            // 0..127
    int lc = (tid & 1) * 4;       // 0 or 4
    const float* Ap = A  + (size_t)(bm + lr) * K + lc;
    const float* Bp = Bm + (size_t)(bn + lr) * K + lc;
    int ty = tid >> 4, tx = tid & 15;
    float acc[8][8];
    #pragma unroll
    for (int i = 0; i < 8; i++)
        #pragma unroll
        for (int j = 0; j < 8; j++) acc[i][j] = 0.f;

    for (int kt = 0; kt < K; kt += 8) {
        float4 av = *(const float4*)(Ap + kt);
        float4 bv = *(const float4*)(Bp + kt);
        As[lc+0][lr] = av.x; As[lc+1][lr] = av.y; As[lc+2][lr] = av.z; As[lc+3][lr] = av.w;
        Bs[lc+0][lr] = bv.x; Bs[lc+1][lr] = bv.y; Bs[lc+2][lr] = bv.z; Bs[lc+3][lr] = bv.w;
        __syncthreads();
        #pragma unroll
        for (int k = 0; k < 8; k++) {
            float4 a0 = *(const float4*)&As[k][ty*8];
            float4 a1 = *(const float4*)&As[k][ty*8+4];
            float4 b0 = *(const float4*)&Bs[k][tx*8];
            float4 b1 = *(const float4*)&Bs[k][tx*8+4];
            float ar[8] = {a0.x,a0.y,a0.z,a0.w,a1.x,a1.y,a1.z,a1.w};
            float br[8] = {b0.x,b0.y,b0.z,b0.w,b1.x,b1.y,b1.z,b1.w};
            #pragma unroll
            for (int i = 0; i < 8; i++)
                #pragma unroll
                for (int j = 0; j < 8; j++)
                    acc[i][j] = fmaf(ar[i], br[j], acc[i][j]);
        }
        __syncthreads();
    }
    #pragma unroll
    for (int i = 0; i < 8; i++) {
        float* crow = C + (size_t)(bm + ty*8 + i) * N + bn + tx*8;
        float4 v0; v0.x = acc[i][0]; v0.y = acc[i][1]; v0.z = acc[i][2]; v0.w = acc[i][3];
        float4 v1; v1.x = acc[i][4]; v1.y = acc[i][5]; v1.z = acc[i][6]; v1.w = acc[i][7];
        *(float4*)crow       = v0;
        *(float4*)(crow + 4) = v1;
    }
}

// ---------------- fused RMSNorm + RoPE + scatter to q/k/v ------------------
// grid (NTOK, 24): heads 0..15 = q, 16..19 = k, 20..23 = v. block = 128 (=DH)
__global__ __launch_bounds__(128) void rmsnorm_rope(
    const int* __restrict__ pos,
    const float* __restrict__ qw, const float* __restrict__ kw)
{
    int token = blockIdx.x;
    int h = blockIdx.y;
    int d = threadIdx.x;
    int b = token / QLEN, q = token % QLEN;

    if (h >= 20) {  // V: straight copy (entire block uniform)
        int hv = h - 20;
        g_v[(((size_t)b*HKV + hv)*QLEN + q)*DH + d] =
            g_qkv[(size_t)token*QKVN + HQ*DH + HKV*DH + hv*DH + d];
        return;
    }
    bool isq = (h < 16);
    int off = isq ? h*DH : HQ*DH + (h-16)*DH;
    float x = g_qkv[(size_t)token*QKVN + off + d];

    __shared__ float red[4];
    __shared__ float sx[128];
    float s = x * x;
    #pragma unroll
    for (int o = 16; o; o >>= 1) s += __shfl_xor_sync(0xffffffffu, s, o);
    if ((d & 31) == 0) red[d >> 5] = s;
    __syncthreads();
    float tot = red[0] + red[1] + red[2] + red[3];
    float r = rsqrtf(tot * (1.0f/DH) + 1e-6f);
    const float* w = isq ? qw : kw;
    float xn = x * r * w[d];
    sx[d] = xn;
    __syncthreads();

    float p = (float)pos[token];
    int i = d & 63;
    float invf = exp2f(-((float)i) * (log2f(1.0e6f) / 64.0f));
    float ang = p * invf;
    float c = cosf(ang), sn = sinf(ang);
    float outv = (d < 64) ? (sx[d]*c - sx[d+64]*sn)
                          : (sx[d]*c + sx[d-64]*sn);
    if (isq) g_q[(((size_t)b*HQ  + h     )*QLEN + q)*DH + d] = outv;
    else     g_k[(((size_t)b*HKV + (h-16))*QLEN + q)*DH + d] = outv;
}

// ---------------- flash attention (fp32, causal, GQA) ----------------------
#define FBM 64
#define FBN 64
#define SD  132   // padded row stride to break bank conflicts
#define FLASH_SMEM ((3*FBM*SD + FBM*65 + 3*FBM) * 4)

__global__ __launch_bounds__(256) void flash_attn()
{
    extern __shared__ float sm_[];
    float* sQ  = sm_;
    float* sK  = sQ + FBM*SD;
    float* sV  = sK + FBN*SD;
    float* sS  = sV + FBN*SD;       // FBM x 65
    float* sMx = sS + FBM*65;
    float* sL  = sMx + FBM;
    float* sA  = sL + FBM;

    int tid = threadIdx.x;
    int qt = blockIdx.x, h = blockIdx.y, b = blockIdx.z;
    int hkv = h >> 2;   // rep = 4

    const float* Qg = g_q + (((size_t)b*HQ  + h  )*QLEN + qt*FBM)*DH;
    const float* Kg = g_k + (((size_t)b*HKV + hkv)*QLEN)*DH;
    const float* Vg = g_v + (((size_t)b*HKV + hkv)*QLEN)*DH;

    #pragma unroll
    for (int it = 0; it < 8; it++) {
        int e = tid + it*256;
        int row = e >> 5, c4 = (e & 31) << 2;
        *(float4*)&sQ[row*SD + c4] = *(const float4*)&Qg[row*DH + c4];
    }
    if (tid < FBM) { sMx[tid] = -1e30f; sL[tid] = 0.f; }

    float o[8][4];
    #pragma unroll
    for (int i = 0; i < 8; i++)
        #pragma unroll
        for (int j = 0; j < 4; j++) o[i][j] = 0.f;

    int rg = tid >> 5;            // row group: 8 rows each
    int cg = (tid & 31) << 2;     // col base: 4 cols
    const float scale = 0.08838834764831845f;  // 1/sqrt(128)
    int ty = tid >> 4, tx = tid & 15;

    for (int kb = 0; kb <= qt; kb++) {
        __syncthreads();   // K/V smem reuse barrier (also covers Q-load on kb=0)
        #pragma unroll
        for (int it = 0; it < 8; it++) {
            int e = tid + it*256;
            int row = e >> 5, c4 = (e & 31) << 2;
            *(float4*)&sK[row*SD + c4] = *(const float4*)&Kg[((size_t)kb*FBN + row)*DH + c4];
            *(float4*)&sV[row*SD + c4] = *(const float4*)&Vg[((size_t)kb*FBN + row)*DH + c4];
        }
        __syncthreads();

        // S = Q K^T : thread computes 4x4 tile
        float acc[4][4];
        #pragma unroll
        for (int a = 0; a < 4; a++)
            #pragma unroll
            for (int c = 0; c < 4; c++) acc[a][c] = 0.f;
        #pragma unroll 4
        for (int k = 0; k < DH; k += 4) {
            float4 qv[4], kv[4];
            #pragma unroll
            for (int a = 0; a < 4; a++) qv[a] = *(const float4*)&sQ[(ty*4+a)*SD + k];
            #pragma unroll
            for (int c = 0; c < 4; c++) kv[c] = *(const float4*)&sK[(tx*4+c)*SD + k];
            #pragma unroll
            for (int a = 0; a < 4; a++)
                #pragma unroll
                for (int c = 0; c < 4; c++)
                    acc[a][c] += qv[a].x*kv[c].x + qv[a].y*kv[c].y
                               + qv[a].z*kv[c].z + qv[a].w*kv[c].w;
        }
        #pragma unroll
        for (int a = 0; a < 4; a++) {
            int grow = qt*FBM + ty*4 + a;
            #pragma unroll
            for (int c = 0; c < 4; c++) {
                int gcol = kb*FBN + tx*4 + c;
                sS[(ty*4+a)*65 + tx*4+c] = (gcol <= grow) ? acc[a][c]*scale : -1e30f;
            }
        }
        __syncthreads();

        // online softmax, one thread per row
        if (tid < FBM) {
            int i = tid;
            float m = sMx[i], mn = m;
            #pragma unroll 8
            for (int j = 0; j < FBN; j++) mn = fmaxf(mn, sS[i*65+j]);
            float al = __expf(m - mn);
            float sum = 0.f;
            #pragma unroll 8
            for (int j = 0; j < FBN; j++) {
                float pij = __expf(sS[i*65+j] - mn);
                sS[i*65+j] = pij;
                sum += pij;
            }
            sL[i] = sL[i]*al + sum;
            sMx[i] = mn;
            sA[i] = al;
        }
        __syncthreads();

        // O = O*alpha + P*V
        #pragma unroll
        for (int i = 0; i < 8; i++) {
            float al = sA[rg*8 + i];
            #pragma unroll
            for (int c = 0; c < 4; c++) o[i][c] *= al;
        }
        #pragma unroll 4
        for (int j = 0; j < FBN; j++) {
            float4 v4 = *(const float4*)&sV[j*SD + cg];
            #pragma unroll
            for (int i = 0; i < 8; i++) {
                float p = sS[(rg*8+i)*65 + j];
                o[i][0] = fmaf(p, v4.x, o[i][0]);
                o[i][1] = fmaf(p, v4.y, o[i][1]);
                o[i][2] = fmaf(p, v4.z, o[i][2]);
                o[i][3] = fmaf(p, v4.w, o[i][3]);
            }
        }
    }
    __syncthreads();

    #pragma unroll
    for (int i = 0; i < 8; i++) {
        int row = rg*8 + i;
        float inv = 1.0f / sL[row];
        int q = qt*FBM + row;
        float4 v;
        v.x = o[i][0]*inv; v.y = o[i][1]*inv; v.z = o[i][2]*inv; v.w = o[i][3]*inv;
        *(float4*)&g_attn[((size_t)(b*QLEN + q))*(HQ*DH) + h*DH + cg] = v;
    }
}

// ---------------------------------------------------------------------------
extern "C" void kernel_launch(void* const* d_in, const int* in_sizes, int n_in,
                              void* d_out, int out_size)
{
    const int*   positions = (const int*)  d_in[0];
    const float* hidden    = (const float*)d_in[1];
    // d_in[2]=k_cache, d_in[3]=v_cache: zeros with start=0 -> fully overwritten, unused
    const float* wqkv      = (const float*)d_in[4];
    const float* wo        = (const float*)d_in[5];
    const float* qw        = (const float*)d_in[6];
    const float* kw        = (const float*)d_in[7];
    float* out = (float*)d_out;

    float *p_qkv, *p_attn;
    cudaGetSymbolAddress((void**)&p_qkv,  g_qkv);
    cudaGetSymbolAddress((void**)&p_attn, g_attn);

    // 1) QKV projection: [4096,3072] = hidden[4096,2048] @ wqkv^T
    sgemm_nt<<<dim3(QKVN/128, NTOK/128), 256>>>(hidden, wqkv, p_qkv, NTOK, QKVN, HID);

    // 2) RMSNorm + RoPE + scatter
    rmsnorm_rope<<<dim3(NTOK, 24), 128>>>(positions, qw, kw);

    // 3) causal GQA flash attention
    cudaFuncSetAttribute(flash_attn, cudaFuncAttributeMaxDynamicSharedMemorySize, FLASH_SMEM);
    flash_attn<<<dim3(QLEN/FBM, HQ, B_), 256, FLASH_SMEM>>>();

    // 4) output projection: [4096,2048] = attn[4096,2048] @ wo^T
    sgemm_nt<<<dim3(HID/128, NTOK/128), 256>>>(p_attn, wo, out, NTOK, HID, HID);
}

// round 8
// speedup vs baseline: 1.0006x; 1.0002x over previous
#include <cuda_runtime.h>
#include <math.h>

#define B_    2
#define QLEN  2048
#define HID   2048
#define HQ    16
#define HKV   4
#define DH    128
#define QKVN  (HQ*DH + 2*HKV*DH)   /* 3072 */
#define NTOK  (B_*QLEN)            /* 4096 */

// ---------------- scratch (device globals: allocation-free) ----------------
__device__ float g_qkv [NTOK * QKVN];            // 50.3 MB
__device__ float g_q   [B_ * HQ  * QLEN * DH];   // 33.5 MB
__device__ float g_k   [B_ * HKV * QLEN * DH];   //  8.4 MB
__device__ float g_v   [B_ * HKV * QLEN * DH];   //  8.4 MB
__device__ float g_attn[NTOK * HQ * DH];         // 33.5 MB

// ---------------- SGEMM: C[M,N] = A[M,K] * B[N,K]^T (both row-major) -------
// 128x128 tile, BK=8, 256 threads, 8x8 per thread.
__global__ __launch_bounds__(256) void sgemm_nt(
    const float* __restrict__ A, const float* __restrict__ Bm,
    float* __restrict__ C, int M, int N, int K)
{
    __shared__ float As[8][128];
    __shared__ float Bs[8][128];
    int tid = threadIdx.x;
    int bm = blockIdx.y * 128;
    int bn = blockIdx.x * 128;
    int lr = tid >> 1;            // 0..127
    int lc = (tid & 1) * 4;       // 0 or 4
    const float* Ap = A  + (size_t)(bm + lr) * K + lc;
    const float* Bp = Bm + (size_t)(bn + lr) * K + lc;
    int ty = tid >> 4, tx = tid & 15;
    float acc[8][8];
    #pragma unroll
    for (int i = 0; i < 8; i++)
        #pragma unroll
        for (int j = 0; j < 8; j++) acc[i][j] = 0.f;

    for (int kt = 0; kt < K; kt += 8) {
        float4 av = *(const float4*)(Ap + kt);
        float4 bv = *(const float4*)(Bp + kt);
        As[lc+0][lr] = av.x; As[lc+1][lr] = av.y; As[lc+2][lr] = av.z; As[lc+3][lr] = av.w;
        Bs[lc+0][lr] = bv.x; Bs[lc+1][lr] = bv.y; Bs[lc+2][lr] = bv.z; Bs[lc+3][lr] = bv.w;
        __syncthreads();
        #pragma unroll
        for (int k = 0; k < 8; k++) {
            float4 a0 = *(const float4*)&As[k][ty*8];
            float4 a1 = *(const float4*)&As[k][ty*8+4];
            float4 b0 = *(const float4*)&Bs[k][tx*8];
            float4 b1 = *(const float4*)&Bs[k][tx*8+4];
            float ar[8] = {a0.x,a0.y,a0.z,a0.w,a1.x,a1.y,a1.z,a1.w};
            float br[8] = {b0.x,b0.y,b0.z,b0.w,b1.x,b1.y,b1.z,b1.w};
            #pragma unroll
            for (int i = 0; i < 8; i++)
                #pragma unroll
                for (int j = 0; j < 8; j++)
                    acc[i][j] = fmaf(ar[i], br[j], acc[i][j]);
        }
        __syncthreads();
    }
    #pragma unroll
    for (int i = 0; i < 8; i++) {
        float* crow = C + (size_t)(bm + ty*8 + i) * N + bn + tx*8;
        float4 v0; v0.x = acc[i][0]; v0.y = acc[i][1]; v0.z = acc[i][2]; v0.w = acc[i][3];
        float4 v1; v1.x = acc[i][4]; v1.y = acc[i][5]; v1.z = acc[i][6]; v1.w = acc[i][7];
        *(float4*)crow       = v0;
        *(float4*)(crow + 4) = v1;
    }
}

// ---------------- fused RMSNorm + RoPE + scatter to q/k/v ------------------
// grid (NTOK, 24): heads 0..15 = q, 16..19 = k, 20..23 = v. block = 128 (=DH)
__global__ __launch_bounds__(128) void rmsnorm_rope(
    const int* __restrict__ pos,
    const float* __restrict__ qw, const float* __restrict__ kw)
{
    int token = blockIdx.x;
    int h = blockIdx.y;
    int d = threadIdx.x;
    int b = token / QLEN, q = token % QLEN;

    if (h >= 20) {  // V: straight copy (entire block uniform)
        int hv = h - 20;
        g_v[(((size_t)b*HKV + hv)*QLEN + q)*DH + d] =
            g_qkv[(size_t)token*QKVN + HQ*DH + HKV*DH + hv*DH + d];
        return;
    }
    bool isq = (h < 16);
    int off = isq ? h*DH : HQ*DH + (h-16)*DH;
    float x = g_qkv[(size_t)token*QKVN + off + d];

    __shared__ float red[4];
    __shared__ float sx[128];
    float s = x * x;
    #pragma unroll
    for (int o = 16; o; o >>= 1) s += __shfl_xor_sync(0xffffffffu, s, o);
    if ((d & 31) == 0) red[d >> 5] = s;
    __syncthreads();
    float tot = red[0] + red[1] + red[2] + red[3];
    float r = rsqrtf(tot * (1.0f/DH) + 1e-6f);
    const float* w = isq ? qw : kw;
    float xn = x * r * w[d];
    sx[d] = xn;
    __syncthreads();

    float p = (float)pos[token];
    int i = d & 63;
    float invf = exp2f(-((float)i) * (log2f(1.0e6f) / 64.0f));
    float ang = p * invf;
    float c = cosf(ang), sn = sinf(ang);
    float outv = (d < 64) ? (sx[d]*c - sx[d+64]*sn)
                          : (sx[d]*c + sx[d-64]*sn);
    if (isq) g_q[(((size_t)b*HQ  + h     )*QLEN + q)*DH + d] = outv;
    else     g_k[(((size_t)b*HKV + (h-16))*QLEN + q)*DH + d] = outv;
}

// ---------------- flash attention (fp32, causal, GQA) ----------------------
#define FBM 64
#define FBN 64
#define SD  132   // padded row stride to break bank conflicts
#define FLASH_SMEM ((3*FBM*SD + FBM*65 + 3*FBM) * 4)

__global__ __launch_bounds__(256) void flash_attn()
{
    extern __shared__ float sm_[];
    float* sQ  = sm_;
    float* sK  = sQ + FBM*SD;
    float* sV  = sK + FBN*SD;
    float* sS  = sV + FBN*SD;       // FBM x 65
    float* sMx = sS + FBM*65;
    float* sL  = sMx + FBM;
    float* sA  = sL + FBM;

    int tid = threadIdx.x;
    int qt = blockIdx.x, h = blockIdx.y, b = blockIdx.z;
    int hkv = h >> 2;   // rep = 4

    const float* Qg = g_q + (((size_t)b*HQ  + h  )*QLEN + qt*FBM)*DH;
    const float* Kg = g_k + (((size_t)b*HKV + hkv)*QLEN)*DH;
    const float* Vg = g_v + (((size_t)b*HKV + hkv)*QLEN)*DH;

    #pragma unroll
    for (int it = 0; it < 8; it++) {
        int e = tid + it*256;
        int row = e >> 5, c4 = (e & 31) << 2;
        *(float4*)&sQ[row*SD + c4] = *(const float4*)&Qg[row*DH + c4];
    }
    if (tid < FBM) { sMx[tid] = -1e30f; sL[tid] = 0.f; }

    float o[8][4];
    #pragma unroll
    for (int i = 0; i < 8; i++)
        #pragma unroll
        for (int j = 0; j < 4; j++) o[i][j] = 0.f;

    int rg = tid >> 5;            // row group: 8 rows each
    int cg = (tid & 31) << 2;     // col base: 4 cols
    const float scale = 0.08838834764831845f;  // 1/sqrt(128)
    int ty = tid >> 4, tx = tid & 15;

    for (int kb = 0; kb <= qt; kb++) {
        __syncthreads();   // K/V smem reuse barrier (also covers Q-load on kb=0)
        #pragma unroll
        for (int it = 0; it < 8; it++) {
            int e = tid + it*256;
            int row = e >> 5, c4 = (e & 31) << 2;
            *(float4*)&sK[row*SD + c4] = *(const float4*)&Kg[((size_t)kb*FBN + row)*DH + c4];
            *(float4*)&sV[row*SD + c4] = *(const float4*)&Vg[((size_t)kb*FBN + row)*DH + c4];
        }
        __syncthreads();

        // S = Q K^T : thread computes 4x4 tile
        float acc[4][4];
        #pragma unroll
        for (int a = 0; a < 4; a++)
            #pragma unroll
            for (int c = 0; c < 4; c++) acc[a][c] = 0.f;
        #pragma unroll 4
        for (int k = 0; k < DH; k += 4) {
            float4 qv[4], kv[4];
            #pragma unroll
            for (int a = 0; a < 4; a++) qv[a] = *(const float4*)&sQ[(ty*4+a)*SD + k];
            #pragma unroll
            for (int c = 0; c < 4; c++) kv[c] = *(const float4*)&sK[(tx*4+c)*SD + k];
            #pragma unroll
            for (int a = 0; a < 4; a++)
                #pragma unroll
                for (int c = 0; c < 4; c++)
                    acc[a][c] += qv[a].x*kv[c].x + qv[a].y*kv[c].y
                               + qv[a].z*kv[c].z + qv[a].w*kv[c].w;
        }
        #pragma unroll
        for (int a = 0; a < 4; a++) {
            int grow = qt*FBM + ty*4 + a;
            #pragma unroll
            for (int c = 0; c < 4; c++) {
                int gcol = kb*FBN + tx*4 + c;
                sS[(ty*4+a)*65 + tx*4+c] = (gcol <= grow) ? acc[a][c]*scale : -1e30f;
            }
        }
        __syncthreads();

        // online softmax, one thread per row
        if (tid < FBM) {
            int i = tid;
            float m = sMx[i], mn = m;
            #pragma unroll 8
            for (int j = 0; j < FBN; j++) mn = fmaxf(mn, sS[i*65+j]);
            float al = __expf(m - mn);
            float sum = 0.f;
            #pragma unroll 8
            for (int j = 0; j < FBN; j++) {
                float pij = __expf(sS[i*65+j] - mn);
                sS[i*65+j] = pij;
                sum += pij;
            }
            sL[i] = sL[i]*al + sum;
            sMx[i] = mn;
            sA[i] = al;
        }
        __syncthreads();

        // O = O*alpha + P*V
        #pragma unroll
        for (int i = 0; i < 8; i++) {
            float al = sA[rg*8 + i];
            #pragma unroll
            for (int c = 0; c < 4; c++) o[i][c] *= al;
        }
        #pragma unroll 4
        for (int j = 0; j < FBN; j++) {
            float4 v4 = *(const float4*)&sV[j*SD + cg];
            #pragma unroll
            for (int i = 0; i < 8; i++) {
                float p = sS[(rg*8+i)*65 + j];
                o[i][0] = fmaf(p, v4.x, o[i][0]);
                o[i][1] = fmaf(p, v4.y, o[i][1]);
                o[i][2] = fmaf(p, v4.z, o[i][2]);
                o[i][3] = fmaf(p, v4.w, o[i][3]);
            }
        }
    }
    __syncthreads();

    #pragma unroll
    for (int i = 0; i < 8; i++) {
        int row = rg*8 + i;
        float inv = 1.0f / sL[row];
        int q = qt*FBM + row;
        float4 v;
        v.x = o[i][0]*inv; v.y = o[i][1]*inv; v.z = o[i][2]*inv; v.w = o[i][3]*inv;
        *(float4*)&g_attn[((size_t)(b*QLEN + q))*(HQ*DH) + h*DH + cg] = v;
    }
}

// ---------------------------------------------------------------------------
extern "C" void kernel_launch(void* const* d_in, const int* in_sizes, int n_in,
                              void* d_out, int out_size)
{
    const int*   positions = (const int*)  d_in[0];
    const float* hidden    = (const float*)d_in[1];
    // d_in[2]=k_cache, d_in[3]=v_cache: zeros with start=0 -> fully overwritten, unused
    const float* wqkv      = (const float*)d_in[4];
    const float* wo        = (const float*)d_in[5];
    const float* qw        = (const float*)d_in[6];
    const float* kw        = (const float*)d_in[7];
    float* out = (float*)d_out;

    float *p_qkv, *p_attn;
    cudaGetSymbolAddress((void**)&p_qkv,  g_qkv);
    cudaGetSymbolAddress((void**)&p_attn, g_attn);

    // 1) QKV projection: [4096,3072] = hidden[4096,2048] @ wqkv^T
    sgemm_nt<<<dim3(QKVN/128, NTOK/128), 256>>>(hidden, wqkv, p_qkv, NTOK, QKVN, HID);

    // 2) RMSNorm + RoPE + scatter
    rmsnorm_rope<<<dim3(NTOK, 24), 128>>>(positions, qw, kw);

    // 3) causal GQA flash attention
    cudaFuncSetAttribute(flash_attn, cudaFuncAttributeMaxDynamicSharedMemorySize, FLASH_SMEM);
    flash_attn<<<dim3(QLEN/FBM, HQ, B_), 256, FLASH_SMEM>>>();

    // 4) output projection: [4096,2048] = attn[4096,2048] @ wo^T
    sgemm_nt<<<dim3(HID/128, NTOK/128), 256>>>(p_attn, wo, out, NTOK, HID, HID);
}

// round 9
// speedup vs baseline: 2.7033x; 2.7016x over previous
#include <cuda_runtime.h>
#include <math.h>
#include <stdint.h>

#define B_    2
#define QLEN  2048
#define HID   2048
#define HQ    16
#define HKV   4
#define DH    128
#define QKVN  (HQ*DH + 2*HKV*DH)   /* 3072 */
#define NTOK  (B_*QLEN)            /* 4096 */

// ---------------- scratch (device globals: allocation-free) ----------------
__device__ float g_qkv [NTOK * QKVN];
__device__ float g_q   [B_ * HQ  * QLEN * DH];
__device__ float g_k   [B_ * HKV * QLEN * DH];
__device__ float g_v   [B_ * HKV * QLEN * DH];
__device__ float g_attn[NTOK * HQ * DH];

__device__ __forceinline__ float to_tf32(float x) {
    asm("cvt.rna.tf32.f32 %0, %0;" : "+f"(x));
    return x;
}

__device__ __forceinline__ void mma_tf32(float c[4],
    uint32_t a0, uint32_t a1, uint32_t a2, uint32_t a3,
    uint32_t b0, uint32_t b1)
{
    asm volatile(
        "mma.sync.aligned.m16n8k8.row.col.f32.tf32.tf32.f32 "
        "{%0,%1,%2,%3}, {%4,%5,%6,%7}, {%8,%9}, {%0,%1,%2,%3};"
        : "+f"(c[0]), "+f"(c[1]), "+f"(c[2]), "+f"(c[3])
        : "r"(a0), "r"(a1), "r"(a2), "r"(a3), "r"(b0), "r"(b1));
}

// swizzled smem index, row stride 32 floats (BK=32)
__device__ __forceinline__ int swz32(int m, int k) {
    return (m << 5) + ((((k >> 2) ^ (m & 7)) << 2) | (k & 3));
}
// swizzled smem index, row stride 128 floats
__device__ __forceinline__ int swz128(int m, int k) {
    return (m << 7) + ((((k >> 2) ^ (m & 7)) << 2) | (k & 3));
}

// ---------------- TF32 GEMM: C[M,N] = A[M,K] * B[N,K]^T -------------------
// 128x128 tile, BK=32, 256 threads (8 warps, 2x4), warp tile 64x32.
__global__ __launch_bounds__(256) void gemm_tf32(
    const float* __restrict__ A, const float* __restrict__ Bm,
    float* __restrict__ C, int M, int N, int K)
{
    __shared__ float As[128*32];
    __shared__ float Bs[128*32];
    int tid = threadIdx.x;
    int bm = blockIdx.y * 128, bn = blockIdx.x * 128;
    int lane = tid & 31;
    int wid  = tid >> 5;
    int wm = (wid >> 2) * 64;   // 0 or 64
    int wn = (wid & 3) * 32;    // 0..96
    int r = lane >> 2, c = lane & 3;

    float acc[16][4];
    #pragma unroll
    for (int t = 0; t < 16; t++)
        #pragma unroll
        for (int x = 0; x < 4; x++) acc[t][x] = 0.f;

    for (int kt = 0; kt < K; kt += 32) {
        #pragma unroll
        for (int it = 0; it < 4; it++) {
            int e = tid + it * 256;      // 0..1023
            int row = e >> 3, g = e & 7;
            float4 av = *(const float4*)&A [(size_t)(bm+row)*K + kt + g*4];
            float4 bv = *(const float4*)&Bm[(size_t)(bn+row)*K + kt + g*4];
            int gs = (g ^ (row & 7)) * 4;
            As[row*32+gs+0] = to_tf32(av.x); As[row*32+gs+1] = to_tf32(av.y);
            As[row*32+gs+2] = to_tf32(av.z); As[row*32+gs+3] = to_tf32(av.w);
            Bs[row*32+gs+0] = to_tf32(bv.x); Bs[row*32+gs+1] = to_tf32(bv.y);
            Bs[row*32+gs+2] = to_tf32(bv.z); Bs[row*32+gs+3] = to_tf32(bv.w);
        }
        __syncthreads();
        #pragma unroll
        for (int s = 0; s < 4; s++) {
            int kc = s * 8;
            uint32_t af[4][4], bf[4][2];
            #pragma unroll
            for (int i = 0; i < 4; i++) {
                int m0 = wm + i*16 + r;
                af[i][0] = __float_as_uint(As[swz32(m0,   kc+c)]);
                af[i][1] = __float_as_uint(As[swz32(m0+8, kc+c)]);
                af[i][2] = __float_as_uint(As[swz32(m0,   kc+c+4)]);
                af[i][3] = __float_as_uint(As[swz32(m0+8, kc+c+4)]);
            }
            #pragma unroll
            for (int j = 0; j < 4; j++) {
                int n0 = wn + j*8 + r;
                bf[j][0] = __float_as_uint(Bs[swz32(n0, kc+c)]);
                bf[j][1] = __float_as_uint(Bs[swz32(n0, kc+c+4)]);
            }
            #pragma unroll
            for (int i = 0; i < 4; i++)
                #pragma unroll
                for (int j = 0; j < 4; j++)
                    mma_tf32(acc[i*4+j], af[i][0],af[i][1],af[i][2],af[i][3],
                             bf[j][0], bf[j][1]);
        }
        __syncthreads();
    }
    #pragma unroll
    for (int i = 0; i < 4; i++) {
        int row0 = bm + wm + i*16 + r;
        #pragma unroll
        for (int j = 0; j < 4; j++) {
            int col = bn + wn + j*8 + c*2;
            float2 v0; v0.x = acc[i*4+j][0]; v0.y = acc[i*4+j][1];
            float2 v1; v1.x = acc[i*4+j][2]; v1.y = acc[i*4+j][3];
            *(float2*)&C[(size_t)row0*N + col]     = v0;
            *(float2*)&C[(size_t)(row0+8)*N + col] = v1;
        }
    }
}

// ---------------- fused RMSNorm + RoPE + scatter to q/k/v ------------------
__global__ __launch_bounds__(128) void rmsnorm_rope(
    const int* __restrict__ pos,
    const float* __restrict__ qw, const float* __restrict__ kw)
{
    int token = blockIdx.x;
    int h = blockIdx.y;
    int d = threadIdx.x;
    int b = token / QLEN, q = token % QLEN;

    if (h >= 20) {  // V: straight copy
        int hv = h - 20;
        g_v[(((size_t)b*HKV + hv)*QLEN + q)*DH + d] =
            g_qkv[(size_t)token*QKVN + HQ*DH + HKV*DH + hv*DH + d];
        return;
    }
    bool isq = (h < 16);
    int off = isq ? h*DH : HQ*DH + (h-16)*DH;
    float x = g_qkv[(size_t)token*QKVN + off + d];

    __shared__ float red[4];
    __shared__ float sx[128];
    float s = x * x;
    #pragma unroll
    for (int o = 16; o; o >>= 1) s += __shfl_xor_sync(0xffffffffu, s, o);
    if ((d & 31) == 0) red[d >> 5] = s;
    __syncthreads();
    float tot = red[0] + red[1] + red[2] + red[3];
    float r = rsqrtf(tot * (1.0f/DH) + 1e-6f);
    const float* w = isq ? qw : kw;
    float xn = x * r * w[d];
    sx[d] = xn;
    __syncthreads();

    float p = (float)pos[token];
    int i = d & 63;
    float invf = exp2f(-((float)i) * (log2f(1.0e6f) / 64.0f));
    float ang = p * invf;
    float cc = cosf(ang), sn = sinf(ang);
    float outv = (d < 64) ? (sx[d]*cc - sx[d+64]*sn)
                          : (sx[d]*cc + sx[d-64]*sn);
    if (isq) g_q[(((size_t)b*HQ  + h     )*QLEN + q)*DH + d] = outv;
    else     g_k[(((size_t)b*HKV + (h-16))*QLEN + q)*DH + d] = outv;
}

// ---------------- flash attention (tf32 MMA, causal, GQA) ------------------
#define FBM 64
#define FBN 64
#define FLASH_SMEM ((3*FBM*DH + FBM*65 + 3*FBM) * 4)

__global__ __launch_bounds__(256) void flash_attn()
{
    extern __shared__ float sm_[];
    float* sQ  = sm_;             // 64 x 128 swizzled (tf32)
    float* sK  = sQ + FBM*DH;     // 64 x 128 swizzled (tf32)
    float* sV  = sK + FBN*DH;     // 64 x 128 swizzled (tf32)
    float* sS  = sV + FBN*DH;     // 64 x 65
    float* sMx = sS + FBM*65;
    float* sL  = sMx + FBM;
    float* sA  = sL + FBM;

    int tid = threadIdx.x;
    int lane = tid & 31, wid = tid >> 5;
    int qt = blockIdx.x, h = blockIdx.y, b = blockIdx.z;
    int hkv = h >> 2;

    const float* Qg = g_q + (((size_t)b*HQ  + h  )*QLEN + qt*FBM)*DH;
    const float* Kg = g_k + (((size_t)b*HKV + hkv)*QLEN)*DH;
    const float* Vg = g_v + (((size_t)b*HKV + hkv)*QLEN)*DH;

    // load Q (tf32, swizzled)
    #pragma unroll
    for (int it = 0; it < 8; it++) {
        int e = tid + it*256;
        int row = e >> 5, g = e & 31;
        float4 v = *(const float4*)&Qg[row*DH + g*4];
        int gs = (g ^ (row & 7)) * 4;
        sQ[row*DH+gs+0] = to_tf32(v.x); sQ[row*DH+gs+1] = to_tf32(v.y);
        sQ[row*DH+gs+2] = to_tf32(v.z); sQ[row*DH+gs+3] = to_tf32(v.w);
    }
    if (tid < FBM) { sMx[tid] = -1e30f; sL[tid] = 0.f; }

    int r = lane >> 2, c = lane & 3;
    int wm  = (wid >> 2) * 32;   // 0/32 : rows for QK and PV
    int wnS = (wid & 3) * 16;    // 0..48: S cols (keys)
    int wnO = (wid & 3) * 32;    // 0..96: O cols (dh)

    float oacc[8][4];            // 2 m-tiles x 4 n-tiles
    #pragma unroll
    for (int t = 0; t < 8; t++)
        #pragma unroll
        for (int x = 0; x < 4; x++) oacc[t][x] = 0.f;

    const float scale = 0.08838834764831845f;

    for (int kb = 0; kb <= qt; kb++) {
        __syncthreads();  // protects sK/sV/sS reuse; covers Q store on first iter
        #pragma unroll
        for (int it = 0; it < 8; it++) {
            int e = tid + it*256;
            int row = e >> 5, g = e & 31;
            float4 kv = *(const float4*)&Kg[((size_t)kb*FBN + row)*DH + g*4];
            float4 vv = *(const float4*)&Vg[((size_t)kb*FBN + row)*DH + g*4];
            int gs = (g ^ (row & 7)) * 4;
            sK[row*DH+gs+0] = to_tf32(kv.x); sK[row*DH+gs+1] = to_tf32(kv.y);
            sK[row*DH+gs+2] = to_tf32(kv.z); sK[row*DH+gs+3] = to_tf32(kv.w);
            sV[row*DH+gs+0] = to_tf32(vv.x); sV[row*DH+gs+1] = to_tf32(vv.y);
            sV[row*DH+gs+2] = to_tf32(vv.z); sV[row*DH+gs+3] = to_tf32(vv.w);
        }
        __syncthreads();

        // ---- S = Q K^T via tf32 MMA: warp tile 32x16, 2x2 mma tiles ----
        float sacc[4][4];
        #pragma unroll
        for (int t = 0; t < 4; t++)
            #pragma unroll
            for (int x = 0; x < 4; x++) sacc[t][x] = 0.f;
        #pragma unroll
        for (int s = 0; s < 16; s++) {
            int kc = s * 8;
            uint32_t af[2][4], bf[2][2];
            #pragma unroll
            for (int i = 0; i < 2; i++) {
                int m0 = wm + i*16 + r;
                af[i][0] = __float_as_uint(sQ[swz128(m0,   kc+c)]);
                af[i][1] = __float_as_uint(sQ[swz128(m0+8, kc+c)]);
                af[i][2] = __float_as_uint(sQ[swz128(m0,   kc+c+4)]);
                af[i][3] = __float_as_uint(sQ[swz128(m0+8, kc+c+4)]);
            }
            #pragma unroll
            for (int j = 0; j < 2; j++) {
                int n0 = wnS + j*8 + r;
                bf[j][0] = __float_as_uint(sK[swz128(n0, kc+c)]);
                bf[j][1] = __float_as_uint(sK[swz128(n0, kc+c+4)]);
            }
            #pragma unroll
            for (int i = 0; i < 2; i++)
                #pragma unroll
                for (int j = 0; j < 2; j++)
                    mma_tf32(sacc[i*2+j], af[i][0],af[i][1],af[i][2],af[i][3],
                             bf[j][0], bf[j][1]);
        }
        // mask + scale, stage to sS
        #pragma unroll
        for (int i = 0; i < 2; i++) {
            #pragma unroll
            for (int j = 0; j < 2; j++) {
                int rl0 = wm + i*16 + r;
                int cl0 = wnS + j*8 + c*2;
                int grow0 = qt*FBM + rl0, gcol0 = kb*FBN + cl0;
                float* t = sacc[i*2+j];
                sS[rl0*65 + cl0]       = (gcol0   <= grow0  ) ? t[0]*scale : -1e30f;
                sS[rl0*65 + cl0+1]     = (gcol0+1 <= grow0  ) ? t[1]*scale : -1e30f;
                sS[(rl0+8)*65 + cl0]   = (gcol0   <= grow0+8) ? t[2]*scale : -1e30f;
                sS[(rl0+8)*65 + cl0+1] = (gcol0+1 <= grow0+8) ? t[3]*scale : -1e30f;
            }
        }
        __syncthreads();

        // ---- online softmax: 4 threads per row ----
        {
            int row = tid >> 2, part = tid & 3;
            float mo = sMx[row];
            float mx = mo;
            #pragma unroll
            for (int jj = 0; jj < 16; jj++)
                mx = fmaxf(mx, sS[row*65 + part*16 + jj]);
            mx = fmaxf(mx, __shfl_xor_sync(0xffffffffu, mx, 1));
            mx = fmaxf(mx, __shfl_xor_sync(0xffffffffu, mx, 2));
            float sum = 0.f;
            #pragma unroll
            for (int jj = 0; jj < 16; jj++) {
                float p = to_tf32(__expf(sS[row*65 + part*16 + jj] - mx));
                sS[row*65 + part*16 + jj] = p;
                sum += p;
            }
            sum += __shfl_xor_sync(0xffffffffu, sum, 1);
            sum += __shfl_xor_sync(0xffffffffu, sum, 2);
            if (part == 0) {
                float al = __expf(mo - mx);
                sL[row] = sL[row]*al + sum;
                sMx[row] = mx;
                sA[row] = al;
            }
        }
        __syncthreads();

        // ---- O = O*alpha + P V via tf32 MMA: warp tile 32x32, 2x4 tiles ----
        #pragma unroll
        for (int i = 0; i < 2; i++) {
            float al0 = sA[wm + i*16 + r];
            float al1 = sA[wm + i*16 + r + 8];
            #pragma unroll
            for (int j = 0; j < 4; j++) {
                oacc[i*4+j][0] *= al0; oacc[i*4+j][1] *= al0;
                oacc[i*4+j][2] *= al1; oacc[i*4+j][3] *= al1;
            }
        }
        #pragma unroll
        for (int s = 0; s < 8; s++) {
            int kc = s * 8;
            uint32_t af[2][4], bf[4][2];
            #pragma unroll
            for (int i = 0; i < 2; i++) {
                int m0 = wm + i*16 + r;
                af[i][0] = __float_as_uint(sS[m0*65      + kc+c]);
                af[i][1] = __float_as_uint(sS[(m0+8)*65  + kc+c]);
                af[i][2] = __float_as_uint(sS[m0*65      + kc+c+4]);
                af[i][3] = __float_as_uint(sS[(m0+8)*65  + kc+c+4]);
            }
            #pragma unroll
            for (int j = 0; j < 4; j++) {
                int n0 = wnO + j*8 + r;
                bf[j][0] = __float_as_uint(sV[swz128(kc+c,   n0)]);
                bf[j][1] = __float_as_uint(sV[swz128(kc+c+4, n0)]);
            }
            #pragma unroll
            for (int i = 0; i < 2; i++)
                #pragma unroll
                for (int j = 0; j < 4; j++)
                    mma_tf32(oacc[i*4+j], af[i][0],af[i][1],af[i][2],af[i][3],
                             bf[j][0], bf[j][1]);
        }
    }
    __syncthreads();

    // epilogue: O /= L, write to g_attn
    #pragma unroll
    for (int i = 0; i < 2; i++) {
        int rl0 = wm + i*16 + r;
        float inv0 = 1.0f / sL[rl0];
        float inv1 = 1.0f / sL[rl0 + 8];
        int q0 = qt*FBM + rl0;
        #pragma unroll
        for (int j = 0; j < 4; j++) {
            int col = wnO + j*8 + c*2;
            float2 v0; v0.x = oacc[i*4+j][0]*inv0; v0.y = oacc[i*4+j][1]*inv0;
            float2 v1; v1.x = oacc[i*4+j][2]*inv1; v1.y = oacc[i*4+j][3]*inv1;
            *(float2*)&g_attn[((size_t)(b*QLEN + q0  ))*(HQ*DH) + h*DH + col] = v0;
            *(float2*)&g_attn[((size_t)(b*QLEN + q0+8))*(HQ*DH) + h*DH + col] = v1;
        }
    }
}

// ---------------------------------------------------------------------------
extern "C" void kernel_launch(void* const* d_in, const int* in_sizes, int n_in,
                              void* d_out, int out_size)
{
    const int*   positions = (const int*)  d_in[0];
    const float* hidden    = (const float*)d_in[1];
    const float* wqkv      = (const float*)d_in[4];
    const float* wo        = (const float*)d_in[5];
    const float* qw        = (const float*)d_in[6];
    const float* kw        = (const float*)d_in[7];
    float* out = (float*)d_out;

    float *p_qkv, *p_attn;
    cudaGetSymbolAddress((void**)&p_qkv,  g_qkv);
    cudaGetSymbolAddress((void**)&p_attn, g_attn);

    // 1) QKV projection (tf32 MMA)
    gemm_tf32<<<dim3(QKVN/128, NTOK/128), 256>>>(hidden, wqkv, p_qkv, NTOK, QKVN, HID);

    // 2) RMSNorm + RoPE + scatter
    rmsnorm_rope<<<dim3(NTOK, 24), 128>>>(positions, qw, kw);

    // 3) causal GQA flash attention (tf32 MMA)
    cudaFuncSetAttribute(flash_attn, cudaFuncAttributeMaxDynamicSharedMemorySize, FLASH_SMEM);
    flash_attn<<<dim3(QLEN/FBM, HQ, B_), 256, FLASH_SMEM>>>();

    // 4) output projection (tf32 MMA)
    gemm_tf32<<<dim3(HID/128, NTOK/128), 256>>>(p_attn, wo, out, NTOK, HID, HID);
}

// round 10
// speedup vs baseline: 3.8693x; 1.4313x over previous
#include <cuda_runtime.h>
#include <math.h>
#include <stdint.h>

#define B_    2
#define QLEN  2048
#define HID   2048
#define HQ    16
#define HKV   4
#define DH    128
#define QKVN  (HQ*DH + 2*HKV*DH)   /* 3072 */
#define NTOK  (B_*QLEN)            /* 4096 */

// ---------------- scratch (device globals: allocation-free) ----------------
__device__ float g_qkv  [NTOK * QKVN];
__device__ float g_q    [B_ * HQ  * QLEN * DH];
__device__ float g_k    [B_ * HKV * QLEN * DH];
__device__ float g_v    [B_ * HKV * QLEN * DH];
__device__ float g_attn [NTOK * HQ * DH];
__device__ float g_hidr [NTOK * HID];    // tf32-rounded inputs
__device__ float g_wqkvr[QKVN * HID];
__device__ float g_wor  [HID * HID];

__device__ __forceinline__ float to_tf32(float x) {
    asm("cvt.rna.tf32.f32 %0, %0;" : "+f"(x));
    return x;
}
__device__ __forceinline__ uint32_t smem_u32(const void* p) {
    return (uint32_t)__cvta_generic_to_shared(p);
}
#define CP_ASYNC16(dst, src) \
    asm volatile("cp.async.cg.shared.global [%0], [%1], 16;" :: "r"(dst), "l"(src))
#define CP_COMMIT() asm volatile("cp.async.commit_group;")
#define CP_WAIT(n)  asm volatile("cp.async.wait_group %0;" :: "n"(n))

__device__ __forceinline__ void mma_tf32(float c[4],
    uint32_t a0, uint32_t a1, uint32_t a2, uint32_t a3,
    uint32_t b0, uint32_t b1)
{
    asm volatile(
        "mma.sync.aligned.m16n8k8.row.col.f32.tf32.tf32.f32 "
        "{%0,%1,%2,%3}, {%4,%5,%6,%7}, {%8,%9}, {%0,%1,%2,%3};"
        : "+f"(c[0]), "+f"(c[1]), "+f"(c[2]), "+f"(c[3])
        : "r"(a0), "r"(a1), "r"(a2), "r"(a3), "r"(b0), "r"(b1));
}

// ---------------- tf32 rounding prepass ------------------------------------
__global__ __launch_bounds__(256) void round_tf32_vec(
    const float* __restrict__ src, float* __restrict__ dst, int n4)
{
    int i = blockIdx.x * 256 + threadIdx.x;
    if (i < n4) {
        float4 v = ((const float4*)src)[i];
        v.x = to_tf32(v.x); v.y = to_tf32(v.y);
        v.z = to_tf32(v.z); v.w = to_tf32(v.w);
        ((float4*)dst)[i] = v;
    }
}

// ---------------- TF32 GEMM: C[M,N] = A[M,K] * B[N,K]^T --------------------
// 128x128 tile, BK=32, 3-stage cp.async pipeline, 256 threads, warp tile 64x32.
// Inputs must already be tf32-rounded.
#define GST 3
#define GEMM_SMEM (GST * 2 * 128 * 32 * 4)
__global__ __launch_bounds__(256) void gemm_tf32(
    const float* __restrict__ A, const float* __restrict__ Bm,
    float* __restrict__ C, int M, int N, int K)
{
    extern __shared__ float sm_[];
    float* As = sm_;                 // [GST][128*32]
    float* Bs = sm_ + GST * 4096;    // [GST][128*32]

    int tid = threadIdx.x;
    int bm = blockIdx.y * 128, bn = blockIdx.x * 128;
    int lane = tid & 31, wid = tid >> 5;
    int wm = (wid >> 2) * 64, wn = (wid & 3) * 32;
    int r = lane >> 2, c = lane & 3;

    // ---- cp.async src/dst mapping (all swizzle math hoisted) ----
    int lrow = tid >> 3;                 // 0..31
    int lg   = tid & 7;                  // 16B chunk
    const float* ga = A  + (size_t)(bm + lrow) * K + lg * 4;
    const float* gb = Bm + (size_t)(bn + lrow) * K + lg * 4;
    uint32_t soff = (uint32_t)(lrow * 32 + ((lg ^ (lrow & 7)) * 4)) * 4;  // bytes
    uint32_t sa = smem_u32(As) + soff;
    uint32_t sb = smem_u32(Bs) + soff;

    // ---- fragment base offsets (floats, relative to stage base) ----
    int a0[4], b0[4];
    #pragma unroll
    for (int i = 0; i < 4; i++) a0[i] = (wm + i*16 + r) * 32 + c;
    #pragma unroll
    for (int j = 0; j < 4; j++) b0[j] = (wn + j*8  + r) * 32 + c;

    float acc[16][4];
    #pragma unroll
    for (int t = 0; t < 16; t++)
        #pragma unroll
        for (int x = 0; x < 4; x++) acc[t][x] = 0.f;

    int T = K >> 5;
    // prologue: stages 0,1
    #pragma unroll
    for (int pst = 0; pst < 2; pst++) {
        #pragma unroll
        for (int it = 0; it < 4; it++) {
            CP_ASYNC16(sa + pst*16384u + it*4096u, ga + pst*32 + (size_t)it*32*K);
            CP_ASYNC16(sb + pst*16384u + it*4096u, gb + pst*32 + (size_t)it*32*K);
        }
        CP_COMMIT();
    }

    for (int t = 0; t < T; t++) {
        if (t + 2 < T) {
            int st = (t + 2) % GST;
            int kt = (t + 2) * 32;
            #pragma unroll
            for (int it = 0; it < 4; it++) {
                CP_ASYNC16(sa + st*16384u + it*4096u, ga + kt + (size_t)it*32*K);
                CP_ASYNC16(sb + st*16384u + it*4096u, gb + kt + (size_t)it*32*K);
            }
        }
        CP_COMMIT();
        CP_WAIT(2);
        __syncthreads();

        const float* Sa = As + (t % GST) * 4096;
        const float* Sb = Bs + (t % GST) * 4096;
        #pragma unroll
        for (int s = 0; s < 4; s++) {
            int off0 = ((2*s) ^ r) * 4;
            int off1 = off0 ^ 4;
            uint32_t af[4][4], bf[4][2];
            #pragma unroll
            for (int i = 0; i < 4; i++) {
                af[i][0] = __float_as_uint(Sa[a0[i] + off0]);
                af[i][1] = __float_as_uint(Sa[a0[i] + 256 + off0]);
                af[i][2] = __float_as_uint(Sa[a0[i] + off1]);
                af[i][3] = __float_as_uint(Sa[a0[i] + 256 + off1]);
            }
            #pragma unroll
            for (int j = 0; j < 4; j++) {
                bf[j][0] = __float_as_uint(Sb[b0[j] + off0]);
                bf[j][1] = __float_as_uint(Sb[b0[j] + off1]);
            }
            #pragma unroll
            for (int i = 0; i < 4; i++)
                #pragma unroll
                for (int j = 0; j < 4; j++)
                    mma_tf32(acc[i*4+j], af[i][0],af[i][1],af[i][2],af[i][3],
                             bf[j][0], bf[j][1]);
        }
        __syncthreads();
    }

    #pragma unroll
    for (int i = 0; i < 4; i++) {
        int row0 = bm + wm + i*16 + r;
        #pragma unroll
        for (int j = 0; j < 4; j++) {
            int col = bn + wn + j*8 + c*2;
            float2 v0; v0.x = acc[i*4+j][0]; v0.y = acc[i*4+j][1];
            float2 v1; v1.x = acc[i*4+j][2]; v1.y = acc[i*4+j][3];
            *(float2*)&C[(size_t)row0*N + col]     = v0;
            *(float2*)&C[(size_t)(row0+8)*N + col] = v1;
        }
    }
}

// ---------------- fused RMSNorm + RoPE + scatter (tf32-rounded out) --------
__global__ __launch_bounds__(128) void rmsnorm_rope(
    const int* __restrict__ pos,
    const float* __restrict__ qw, const float* __restrict__ kw)
{
    int token = blockIdx.x;
    int h = blockIdx.y;
    int d = threadIdx.x;
    int b = token / QLEN, q = token % QLEN;

    if (h >= 20) {  // V: copy + round
        int hv = h - 20;
        g_v[(((size_t)b*HKV + hv)*QLEN + q)*DH + d] =
            to_tf32(g_qkv[(size_t)token*QKVN + HQ*DH + HKV*DH + hv*DH + d]);
        return;
    }
    bool isq = (h < 16);
    int off = isq ? h*DH : HQ*DH + (h-16)*DH;
    float x = g_qkv[(size_t)token*QKVN + off + d];

    __shared__ float red[4];
    __shared__ float sx[128];
    float s = x * x;
    #pragma unroll
    for (int o = 16; o; o >>= 1) s += __shfl_xor_sync(0xffffffffu, s, o);
    if ((d & 31) == 0) red[d >> 5] = s;
    __syncthreads();
    float tot = red[0] + red[1] + red[2] + red[3];
    float r = rsqrtf(tot * (1.0f/DH) + 1e-6f);
    const float* w = isq ? qw : kw;
    float xn = x * r * w[d];
    sx[d] = xn;
    __syncthreads();

    float p = (float)pos[token];
    int i = d & 63;
    float invf = exp2f(-((float)i) * (log2f(1.0e6f) / 64.0f));
    float ang = p * invf;
    float cc = cosf(ang), sn = sinf(ang);
    float outv = (d < 64) ? (sx[d]*cc - sx[d+64]*sn)
                          : (sx[d]*cc + sx[d-64]*sn);
    outv = to_tf32(outv);
    if (isq) g_q[(((size_t)b*HQ  + h     )*QLEN + q)*DH + d] = outv;
    else     g_k[(((size_t)b*HKV + (h-16))*QLEN + q)*DH + d] = outv;
}

// ---------------- flash attention (tf32 MMA + cp.async ring, causal) -------
#define FBM 64
#define FBN 64
// sQ 8192 + sK 2*8192 + sV 2*8192 + sS 64*65 + 3*64
#define FLASH_SMEM ((5*FBM*DH + FBM*65 + 3*FBM) * 4)

__global__ __launch_bounds__(256) void flash_attn()
{
    extern __shared__ float sm_[];
    float* sQ  = sm_;                  // 64 x 128 swizzled
    float* sK  = sQ + FBM*DH;          // 2 stages
    float* sV  = sK + 2*FBN*DH;        // 2 stages
    float* sS  = sV + 2*FBN*DH;        // 64 x 65
    float* sMx = sS + FBM*65;
    float* sL  = sMx + FBM;
    float* sA  = sL + FBM;

    int tid = threadIdx.x;
    int lane = tid & 31, wid = tid >> 5;
    int qt = blockIdx.x, h = blockIdx.y, b = blockIdx.z;
    int hkv = h >> 2;

    const float* Qg = g_q + (((size_t)b*HQ  + h  )*QLEN + qt*FBM)*DH;
    const float* Kg = g_k + (((size_t)b*HKV + hkv)*QLEN)*DH;
    const float* Vg = g_v + (((size_t)b*HKV + hkv)*QLEN)*DH;

    // cp.async mapping: row0 = tid>>5 (+8*it), chunk g = tid&31
    int row0 = tid >> 5, g32 = tid & 31;
    uint32_t dq = smem_u32(sQ) + (uint32_t)(row0*DH + ((g32 ^ row0) * 4)) * 4;
    uint32_t dk = smem_u32(sK) + (uint32_t)(row0*DH + ((g32 ^ row0) * 4)) * 4;
    uint32_t dv = smem_u32(sV) + (uint32_t)(row0*DH + ((g32 ^ row0) * 4)) * 4;
    const float* gq = Qg + row0*DH + g32*4;
    const float* gk = Kg + row0*DH + g32*4;
    const float* gv = Vg + row0*DH + g32*4;

    // prologue: Q + KV stage 0 in one group
    #pragma unroll
    for (int it = 0; it < 8; it++) CP_ASYNC16(dq + it*4096u, gq + it*1024);
    #pragma unroll
    for (int it = 0; it < 8; it++) {
        CP_ASYNC16(dk + it*4096u, gk + it*1024);
        CP_ASYNC16(dv + it*4096u, gv + it*1024);
    }
    CP_COMMIT();

    if (tid < FBM) { sMx[tid] = -1e30f; sL[tid] = 0.f; }

    int r = lane >> 2, c = lane & 3;
    int wm  = (wid >> 2) * 32;
    int wnS = (wid & 3) * 16;
    int wnO = (wid & 3) * 32;

    // fragment base offsets
    int qa0[2], kb0[2], va0[2];
    #pragma unroll
    for (int i = 0; i < 2; i++) qa0[i] = (wm + i*16 + r) * DH + c;
    #pragma unroll
    for (int j = 0; j < 2; j++) kb0[j] = (wnS + j*8 + r) * DH + c;
    int vcol0[4], vcol1[4];
    #pragma unroll
    for (int j = 0; j < 4; j++) {
        int vx = (wnO >> 2) + 2*j + (r >> 2);
        vcol0[j] = ((vx ^ c) * 4) + (r & 3);
        vcol1[j] = ((vx ^ (c + 4)) * 4) + (r & 3);
    }
    #pragma unroll
    for (int i = 0; i < 2; i++) va0[i] = 0; // unused placeholder

    float oacc[8][4];
    #pragma unroll
    for (int t = 0; t < 8; t++)
        #pragma unroll
        for (int x = 0; x < 4; x++) oacc[t][x] = 0.f;

    const float scale = 0.08838834764831845f;

    for (int kb = 0; kb <= qt; kb++) {
        __syncthreads();   // prior PV reads of the buffer we are about to refill
        if (kb + 1 <= qt) {
            uint32_t stoff = (uint32_t)(((kb + 1) & 1) * FBN * DH) * 4;
            const float* gk1 = gk + (size_t)(kb + 1) * FBN * DH;
            const float* gv1 = gv + (size_t)(kb + 1) * FBN * DH;
            #pragma unroll
            for (int it = 0; it < 8; it++) {
                CP_ASYNC16(dk + stoff + it*4096u, gk1 + it*1024);
                CP_ASYNC16(dv + stoff + it*4096u, gv1 + it*1024);
            }
        }
        CP_COMMIT();
        CP_WAIT(1);
        __syncthreads();

        const float* Kb = sK + (kb & 1) * FBN * DH;
        const float* Vb = sV + (kb & 1) * FBN * DH;

        // ---- S = Q K^T ----
        float sacc[4][4];
        #pragma unroll
        for (int t = 0; t < 4; t++)
            #pragma unroll
            for (int x = 0; x < 4; x++) sacc[t][x] = 0.f;
        #pragma unroll
        for (int s = 0; s < 16; s++) {
            int off0 = ((2*s) ^ r) * 4;
            int off1 = off0 ^ 4;
            uint32_t af[2][4], bf[2][2];
            #pragma unroll
            for (int i = 0; i < 2; i++) {
                af[i][0] = __float_as_uint(sQ[qa0[i] + off0]);
                af[i][1] = __float_as_uint(sQ[qa0[i] + 8*DH + off0]);
                af[i][2] = __float_as_uint(sQ[qa0[i] + off1]);
                af[i][3] = __float_as_uint(sQ[qa0[i] + 8*DH + off1]);
            }
            #pragma unroll
            for (int j = 0; j < 2; j++) {
                bf[j][0] = __float_as_uint(Kb[kb0[j] + off0]);
                bf[j][1] = __float_as_uint(Kb[kb0[j] + off1]);
            }
            #pragma unroll
            for (int i = 0; i < 2; i++)
                #pragma unroll
                for (int j = 0; j < 2; j++)
                    mma_tf32(sacc[i*2+j], af[i][0],af[i][1],af[i][2],af[i][3],
                             bf[j][0], bf[j][1]);
        }
        #pragma unroll
        for (int i = 0; i < 2; i++) {
            #pragma unroll
            for (int j = 0; j < 2; j++) {
                int rl0 = wm + i*16 + r;
                int cl0 = wnS + j*8 + c*2;
                int grow0 = qt*FBM + rl0, gcol0 = kb*FBN + cl0;
                float* t = sacc[i*2+j];
                sS[rl0*65 + cl0]       = (gcol0   <= grow0  ) ? t[0]*scale : -1e30f;
                sS[rl0*65 + cl0+1]     = (gcol0+1 <= grow0  ) ? t[1]*scale : -1e30f;
                sS[(rl0+8)*65 + cl0]   = (gcol0   <= grow0+8) ? t[2]*scale : -1e30f;
                sS[(rl0+8)*65 + cl0+1] = (gcol0+1 <= grow0+8) ? t[3]*scale : -1e30f;
            }
        }
        __syncthreads();

        // ---- online softmax: 4 threads per row ----
        {
            int row = tid >> 2, part = tid & 3;
            float mo = sMx[row];
            float mx = mo;
            #pragma unroll
            for (int jj = 0; jj < 16; jj++)
                mx = fmaxf(mx, sS[row*65 + part*16 + jj]);
            mx = fmaxf(mx, __shfl_xor_sync(0xffffffffu, mx, 1));
            mx = fmaxf(mx, __shfl_xor_sync(0xffffffffu, mx, 2));
            float sum = 0.f;
            #pragma unroll
            for (int jj = 0; jj < 16; jj++) {
                float p = to_tf32(__expf(sS[row*65 + part*16 + jj] - mx));
                sS[row*65 + part*16 + jj] = p;
                sum += p;
            }
            sum += __shfl_xor_sync(0xffffffffu, sum, 1);
            sum += __shfl_xor_sync(0xffffffffu, sum, 2);
            if (part == 0) {
                float al = __expf(mo - mx);
                sL[row] = sL[row]*al + sum;
                sMx[row] = mx;
                sA[row] = al;
            }
        }
        __syncthreads();

        // ---- O = O*alpha + P V ----
        #pragma unroll
        for (int i = 0; i < 2; i++) {
            float al0 = sA[wm + i*16 + r];
            float al1 = sA[wm + i*16 + r + 8];
            #pragma unroll
            for (int j = 0; j < 4; j++) {
                oacc[i*4+j][0] *= al0; oacc[i*4+j][1] *= al0;
                oacc[i*4+j][2] *= al1; oacc[i*4+j][3] *= al1;
            }
        }
        #pragma unroll
        for (int s = 0; s < 8; s++) {
            int kc = s * 8;
            uint32_t af[2][4], bf[4][2];
            #pragma unroll
            for (int i = 0; i < 2; i++) {
                int m0 = wm + i*16 + r;
                af[i][0] = __float_as_uint(sS[m0*65      + kc+c]);
                af[i][1] = __float_as_uint(sS[(m0+8)*65  + kc+c]);
                af[i][2] = __float_as_uint(sS[m0*65      + kc+c+4]);
                af[i][3] = __float_as_uint(sS[(m0+8)*65  + kc+c+4]);
            }
            int vr0 = (kc + c) * DH, vr1 = (kc + c + 4) * DH;
            #pragma unroll
            for (int j = 0; j < 4; j++) {
                bf[j][0] = __float_as_uint(Vb[vr0 + vcol0[j]]);
                bf[j][1] = __float_as_uint(Vb[vr1 + vcol1[j]]);
            }
            #pragma unroll
            for (int i = 0; i < 2; i++)
                #pragma unroll
                for (int j = 0; j < 4; j++)
                    mma_tf32(oacc[i*4+j], af[i][0],af[i][1],af[i][2],af[i][3],
                             bf[j][0], bf[j][1]);
        }
    }
    __syncthreads();

    // epilogue: O /= L, round to tf32 (feeds WO GEMM), write
    #pragma unroll
    for (int i = 0; i < 2; i++) {
        int rl0 = wm + i*16 + r;
        float inv0 = 1.0f / sL[rl0];
        float inv1 = 1.0f / sL[rl0 + 8];
        int q0 = qt*FBM + rl0;
        #pragma unroll
        for (int j = 0; j < 4; j++) {
            int col = wnO + j*8 + c*2;
            float2 v0, v1;
            v0.x = to_tf32(oacc[i*4+j][0]*inv0); v0.y = to_tf32(oacc[i*4+j][1]*inv0);
            v1.x = to_tf32(oacc[i*4+j][2]*inv1); v1.y = to_tf32(oacc[i*4+j][3]*inv1);
            *(float2*)&g_attn[((size_t)(b*QLEN + q0  ))*(HQ*DH) + h*DH + col] = v0;
            *(float2*)&g_attn[((size_t)(b*QLEN + q0+8))*(HQ*DH) + h*DH + col] = v1;
        }
    }
}

// ---------------------------------------------------------------------------
extern "C" void kernel_launch(void* const* d_in, const int* in_sizes, int n_in,
                              void* d_out, int out_size)
{
    const int*   positions = (const int*)  d_in[0];
    const float* hidden    = (const float*)d_in[1];
    const float* wqkv      = (const float*)d_in[4];
    const float* wo        = (const float*)d_in[5];
    const float* qw        = (const float*)d_in[6];
    const float* kw        = (const float*)d_in[7];
    float* out = (float*)d_out;

    float *p_qkv, *p_attn, *p_hidr, *p_wqkvr, *p_wor;
    cudaGetSymbolAddress((void**)&p_qkv,   g_qkv);
    cudaGetSymbolAddress((void**)&p_attn,  g_attn);
    cudaGetSymbolAddress((void**)&p_hidr,  g_hidr);
    cudaGetSymbolAddress((void**)&p_wqkvr, g_wqkvr);
    cudaGetSymbolAddress((void**)&p_wor,   g_wor);

    cudaFuncSetAttribute(gemm_tf32,  cudaFuncAttributeMaxDynamicSharedMemorySize, GEMM_SMEM);
    cudaFuncSetAttribute(flash_attn, cudaFuncAttributeMaxDynamicSharedMemorySize, FLASH_SMEM);

    // 0) tf32 rounding prepass (enables raw cp.async in GEMMs, keeps RNA accuracy)
    round_tf32_vec<<<(NTOK*HID/4 + 255)/256, 256>>>(hidden, p_hidr, NTOK*HID/4);
    round_tf32_vec<<<(QKVN*HID/4 + 255)/256, 256>>>(wqkv, p_wqkvr, QKVN*HID/4);
    round_tf32_vec<<<(HID*HID/4 + 255)/256, 256>>>(wo, p_wor, HID*HID/4);

    // 1) QKV projection
    gemm_tf32<<<dim3(QKVN/128, NTOK/128), 256, GEMM_SMEM>>>(p_hidr, p_wqkvr, p_qkv, NTOK, QKVN, HID);

    // 2) RMSNorm + RoPE + scatter (tf32-rounded outputs)
    rmsnorm_rope<<<dim3(NTOK, 24), 128>>>(positions, qw, kw);

    // 3) causal GQA flash attention
    flash_attn<<<dim3(QLEN/FBM, HQ, B_), 256, FLASH_SMEM>>>();

    // 4) output projection
    gemm_tf32<<<dim3(HID/128, NTOK/128), 256, GEMM_SMEM>>>(p_attn, p_wor, out, NTOK, HID, HID);
}

// round 16
// speedup vs baseline: 4.2484x; 1.0980x over previous
#include <cuda_runtime.h>
#include <math.h>
#include <stdint.h>

#define B_    2
#define QLEN  2048
#define HID   2048
#define HQ    16
#define HKV   4
#define DH    128
#define QKVN  (HQ*DH + 2*HKV*DH)   /* 3072 */
#define NTOK  (B_*QLEN)            /* 4096 */

// ---------------- scratch (device globals: allocation-free) ----------------
__device__ float g_qkv  [NTOK * QKVN];
__device__ float g_q    [B_ * HQ  * QLEN * DH];
__device__ float g_k    [B_ * HKV * QLEN * DH];
__device__ float g_v    [B_ * HKV * QLEN * DH];
__device__ float g_attn [NTOK * HQ * DH];
__device__ float g_hidr [NTOK * HID];    // tf32-rounded inputs
__device__ float g_wqkvr[QKVN * HID];
__device__ float g_wor  [HID * HID];

__device__ __forceinline__ float to_tf32(float x) {
    asm("cvt.rna.tf32.f32 %0, %0;" : "+f"(x));
    return x;
}
__device__ __forceinline__ uint32_t smem_u32(const void* p) {
    return (uint32_t)__cvta_generic_to_shared(p);
}
#define CP_ASYNC16(dst, src) \
    asm volatile("cp.async.cg.shared.global [%0], [%1], 16;" :: "r"(dst), "l"(src))
#define CP_COMMIT() asm volatile("cp.async.commit_group;")
#define CP_WAIT(n)  asm volatile("cp.async.wait_group %0;" :: "n"(n))

__device__ __forceinline__ void mma_tf32(float c[4],
    uint32_t a0, uint32_t a1, uint32_t a2, uint32_t a3,
    uint32_t b0, uint32_t b1)
{
    asm volatile(
        "mma.sync.aligned.m16n8k8.row.col.f32.tf32.tf32.f32 "
        "{%0,%1,%2,%3}, {%4,%5,%6,%7}, {%8,%9}, {%0,%1,%2,%3};"
        : "+f"(c[0]), "+f"(c[1]), "+f"(c[2]), "+f"(c[3])
        : "r"(a0), "r"(a1), "r"(a2), "r"(a3), "r"(b0), "r"(b1));
}

// ---------------- tf32 rounding prepass ------------------------------------
__global__ __launch_bounds__(256) void round_tf32_vec(
    const float* __restrict__ src, float* __restrict__ dst, int n4)
{
    int i = blockIdx.x * 256 + threadIdx.x;
    if (i < n4) {
        float4 v = ((const float4*)src)[i];
        v.x = to_tf32(v.x); v.y = to_tf32(v.y);
        v.z = to_tf32(v.z); v.w = to_tf32(v.w);
        ((float4*)dst)[i] = v;
    }
}

// ---------------- TF32 GEMM: C[M,N] = A[M,K] * B[N,K]^T --------------------
// 128x128 tile, BK=32, 3-stage cp.async pipeline, 256 threads, warp tile 64x32.
#define GST 3
#define GEMM_SMEM (GST * 2 * 128 * 32 * 4)
__global__ __launch_bounds__(256) void gemm_tf32(
    const float* __restrict__ A, const float* __restrict__ Bm,
    float* __restrict__ C, int M, int N, int K)
{
    extern __shared__ float sm_[];
    float* As = sm_;
    float* Bs = sm_ + GST * 4096;

    int tid = threadIdx.x;
    int bm = blockIdx.y * 128, bn = blockIdx.x * 128;
    int lane = tid & 31, wid = tid >> 5;
    int wm = (wid >> 2) * 64, wn = (wid & 3) * 32;
    int r = lane >> 2, c = lane & 3;

    int lrow = tid >> 3;
    int lg   = tid & 7;
    const float* ga = A  + (size_t)(bm + lrow) * K + lg * 4;
    const float* gb = Bm + (size_t)(bn + lrow) * K + lg * 4;
    uint32_t soff = (uint32_t)(lrow * 32 + ((lg ^ (lrow & 7)) * 4)) * 4;
    uint32_t sa = smem_u32(As) + soff;
    uint32_t sb = smem_u32(Bs) + soff;

    int a0[4], b0[4];
    #pragma unroll
    for (int i = 0; i < 4; i++) a0[i] = (wm + i*16 + r) * 32 + c;
    #pragma unroll
    for (int j = 0; j < 4; j++) b0[j] = (wn + j*8  + r) * 32 + c;

    float acc[16][4];
    #pragma unroll
    for (int t = 0; t < 16; t++)
        #pragma unroll
        for (int x = 0; x < 4; x++) acc[t][x] = 0.f;

    int T = K >> 5;
    #pragma unroll
    for (int pst = 0; pst < 2; pst++) {
        #pragma unroll
        for (int it = 0; it < 4; it++) {
            CP_ASYNC16(sa + pst*16384u + it*4096u, ga + pst*32 + (size_t)it*32*K);
            CP_ASYNC16(sb + pst*16384u + it*4096u, gb + pst*32 + (size_t)it*32*K);
        }
        CP_COMMIT();
    }

    for (int t = 0; t < T; t++) {
        if (t + 2 < T) {
            int st = (t + 2) % GST;
            int kt = (t + 2) * 32;
            #pragma unroll
            for (int it = 0; it < 4; it++) {
                CP_ASYNC16(sa + st*16384u + it*4096u, ga + kt + (size_t)it*32*K);
                CP_ASYNC16(sb + st*16384u + it*4096u, gb + kt + (size_t)it*32*K);
            }
        }
        CP_COMMIT();
        CP_WAIT(2);
        __syncthreads();

        const float* Sa = As + (t % GST) * 4096;
        const float* Sb = Bs + (t % GST) * 4096;
        #pragma unroll
        for (int s = 0; s < 4; s++) {
            int off0 = ((2*s) ^ r) * 4;
            int off1 = off0 ^ 4;
            uint32_t af[4][4], bf[4][2];
            #pragma unroll
            for (int i = 0; i < 4; i++) {
                af[i][0] = __float_as_uint(Sa[a0[i] + off0]);
                af[i][1] = __float_as_uint(Sa[a0[i] + 256 + off0]);
                af[i][2] = __float_as_uint(Sa[a0[i] + off1]);
                af[i][3] = __float_as_uint(Sa[a0[i] + 256 + off1]);
            }
            #pragma unroll
            for (int j = 0; j < 4; j++) {
                bf[j][0] = __float_as_uint(Sb[b0[j] + off0]);
                bf[j][1] = __float_as_uint(Sb[b0[j] + off1]);
            }
            #pragma unroll
            for (int i = 0; i < 4; i++)
                #pragma unroll
                for (int j = 0; j < 4; j++)
                    mma_tf32(acc[i*4+j], af[i][0],af[i][1],af[i][2],af[i][3],
                             bf[j][0], bf[j][1]);
        }
        __syncthreads();
    }

    #pragma unroll
    for (int i = 0; i < 4; i++) {
        int row0 = bm + wm + i*16 + r;
        #pragma unroll
        for (int j = 0; j < 4; j++) {
            int col = bn + wn + j*8 + c*2;
            float2 v0; v0.x = acc[i*4+j][0]; v0.y = acc[i*4+j][1];
            float2 v1; v1.x = acc[i*4+j][2]; v1.y = acc[i*4+j][3];
            *(float2*)&C[(size_t)row0*N + col]     = v0;
            *(float2*)&C[(size_t)(row0+8)*N + col] = v1;
        }
    }
}

// ---------------- fused RMSNorm + RoPE + scatter (tf32-rounded out) --------
__global__ __launch_bounds__(128) void rmsnorm_rope(
    const int* __restrict__ pos,
    const float* __restrict__ qw, const float* __restrict__ kw)
{
    int token = blockIdx.x;
    int h = blockIdx.y;
    int d = threadIdx.x;
    int b = token / QLEN, q = token % QLEN;

    if (h >= 20) {  // V: copy + round
        int hv = h - 20;
        g_v[(((size_t)b*HKV + hv)*QLEN + q)*DH + d] =
            to_tf32(g_qkv[(size_t)token*QKVN + HQ*DH + HKV*DH + hv*DH + d]);
        return;
    }
    bool isq = (h < 16);
    int off = isq ? h*DH : HQ*DH + (h-16)*DH;
    float x = g_qkv[(size_t)token*QKVN + off + d];

    __shared__ float red[4];
    __shared__ float sx[128];
    float s = x * x;
    #pragma unroll
    for (int o = 16; o; o >>= 1) s += __shfl_xor_sync(0xffffffffu, s, o);
    if ((d & 31) == 0) red[d >> 5] = s;
    __syncthreads();
    float tot = red[0] + red[1] + red[2] + red[3];
    float r = rsqrtf(tot * (1.0f/DH) + 1e-6f);
    const float* w = isq ? qw : kw;
    float xn = x * r * w[d];
    sx[d] = xn;
    __syncthreads();

    float p = (float)pos[token];
    int i = d & 63;
    float invf = exp2f(-((float)i) * (log2f(1.0e6f) / 64.0f));
    float ang = p * invf;
    float cc = cosf(ang), sn = sinf(ang);
    float outv = (d < 64) ? (sx[d]*cc - sx[d+64]*sn)
                          : (sx[d]*cc + sx[d-64]*sn);
    outv = to_tf32(outv);
    if (isq) g_q[(((size_t)b*HQ  + h     )*QLEN + q)*DH + d] = outv;
    else     g_k[(((size_t)b*HKV + (h-16))*QLEN + q)*DH + d] = outv;
}

// ---------------- flash attention: Q tile 128, KV 64x2, tf32 MMA -----------
#define FBM 128
#define FBN 64
#define SSTR 66
#define FLASH_SMEM ((FBM*DH + 4*FBN*DH + FBM*SSTR + 3*FBM) * 4)   /* 231936 */

__global__ __launch_bounds__(256) void flash_attn()
{
    extern __shared__ float sm_[];
    float* sQ  = sm_;                      // 128 x 128 swizzled
    float* sK  = sQ + FBM*DH;              // 2 x 64 x 128 swizzled
    float* sV  = sK + 2*FBN*DH;            // 2 x 64 x 128 swizzled
    float* sS  = sV + 2*FBN*DH;            // 128 x 66
    float* sMx = sS + FBM*SSTR;
    float* sL  = sMx + FBM;
    float* sA  = sL + FBM;

    int tid = threadIdx.x;
    int lane = tid & 31, wid = tid >> 5;
    int qt = (int)(gridDim.x - 1 - blockIdx.x);   // longest-first
    int h = blockIdx.y, b = blockIdx.z;
    int hkv = h >> 2;

    const float* Qg = g_q + (((size_t)b*HQ  + h  )*QLEN + qt*FBM)*DH;
    const float* Kg = g_k + (((size_t)b*HKV + hkv)*QLEN)*DH;
    const float* Vg = g_v + (((size_t)b*HKV + hkv)*QLEN)*DH;

    // cp.async mapping: row0 = tid>>5 in 0..7, +8 per chunk-iter keeps row&7
    int row0 = tid >> 5, g32 = tid & 31;
    uint32_t swz = (uint32_t)((g32 ^ row0) * 4);
    uint32_t dq = smem_u32(sQ) + (uint32_t)(row0*DH)*4 + swz*4;
    uint32_t dk = smem_u32(sK) + (uint32_t)(row0*DH)*4 + swz*4;
    uint32_t dv = smem_u32(sV) + (uint32_t)(row0*DH)*4 + swz*4;
    const float* gq = Qg + row0*DH + g32*4;
    const float* gk = Kg + row0*DH + g32*4;
    const float* gv = Vg + row0*DH + g32*4;

    // prologue: Q (128 rows = 16 iters of 8 rows) + K0/V0, single group
    #pragma unroll
    for (int it = 0; it < 16; it++) CP_ASYNC16(dq + it*4096u, gq + it*1024);
    #pragma unroll
    for (int it = 0; it < 8; it++) {
        CP_ASYNC16(dk + it*4096u, gk + it*1024);
        CP_ASYNC16(dv + it*4096u, gv + it*1024);
    }
    CP_COMMIT();

    if (tid < FBM) { sMx[tid] = -1e30f; sL[tid] = 0.f; }

    int r = lane >> 2, c = lane & 3;
    int wm  = (wid >> 1) * 32;       // warp m rows (both QK and PV): 0..96
    int wnS = (wid & 1) * 32;        // QK n cols (keys): 0/32
    int wnO = (wid & 1) * 64;        // PV n cols (dh): 0/64

    // fragment base offsets (row&7 == r for all fragment rows)
    int qa0[2], kb0[4];
    #pragma unroll
    for (int i = 0; i < 2; i++) qa0[i] = (wm + i*16 + r) * DH + c;
    #pragma unroll
    for (int j = 0; j < 4; j++) kb0[j] = (wnS + j*8 + r) * DH + c;
    int vcol0[8], vcol1[8];
    #pragma unroll
    for (int j = 0; j < 8; j++) {
        int vx = (wnO >> 2) + 2*j + (r >> 2);
        vcol0[j] = ((vx ^ c) * 4) + (r & 3);
        vcol1[j] = ((vx ^ (c + 4)) * 4) + (r & 3);
    }

    float oacc[16][4];
    #pragma unroll
    for (int t = 0; t < 16; t++)
        #pragma unroll
        for (int x = 0; x < 4; x++) oacc[t][x] = 0.f;

    const float scale = 0.08838834764831845f;   // 1/sqrt(128)
    int kbmax = 2*qt + 1;

    for (int kb = 0; kb <= kbmax; kb++) {
        __syncthreads();   // prior PV reads of buffer we refill (also covers init)
        if (kb + 1 <= kbmax) {
            uint32_t stoff = (uint32_t)(((kb + 1) & 1) * FBN * DH) * 4;
            const float* gk1 = gk + (size_t)(kb + 1) * FBN * DH;
            const float* gv1 = gv + (size_t)(kb + 1) * FBN * DH;
            #pragma unroll
            for (int it = 0; it < 8; it++) {
                CP_ASYNC16(dk + stoff + it*4096u, gk1 + it*1024);
                CP_ASYNC16(dv + stoff + it*4096u, gv1 + it*1024);
            }
        }
        CP_COMMIT();
        CP_WAIT(1);
        __syncthreads();

        const float* Kb = sK + (kb & 1) * FBN * DH;
        const float* Vb = sV + (kb & 1) * FBN * DH;

        // ---- S = Q K^T : warp tile 32x32 (2 m-tiles x 4 n-tiles) ----
        float sacc[8][4];
        #pragma unroll
        for (int t = 0; t < 8; t++)
            #pragma unroll
            for (int x = 0; x < 4; x++) sacc[t][x] = 0.f;
        #pragma unroll
        for (int s = 0; s < 16; s++) {
            int off0 = ((2*s) ^ r) * 4;
            int off1 = off0 ^ 4;
            uint32_t af[2][4], bf[4][2];
            #pragma unroll
            for (int i = 0; i < 2; i++) {
                af[i][0] = __float_as_uint(sQ[qa0[i] + off0]);
                af[i][1] = __float_as_uint(sQ[qa0[i] + 8*DH + off0]);
                af[i][2] = __float_as_uint(sQ[qa0[i] + off1]);
                af[i][3] = __float_as_uint(sQ[qa0[i] + 8*DH + off1]);
            }
            #pragma unroll
            for (int j = 0; j < 4; j++) {
                bf[j][0] = __float_as_uint(Kb[kb0[j] + off0]);
                bf[j][1] = __float_as_uint(Kb[kb0[j] + off1]);
            }
            #pragma unroll
            for (int i = 0; i < 2; i++)
                #pragma unroll
                for (int j = 0; j < 4; j++)
                    mma_tf32(sacc[i*4+j], af[i][0],af[i][1],af[i][2],af[i][3],
                             bf[j][0], bf[j][1]);
        }
        // mask + scale -> sS
        #pragma unroll
        for (int i = 0; i < 2; i++) {
            #pragma unroll
            for (int j = 0; j < 4; j++) {
                int rl0 = wm + i*16 + r;
                int cl0 = wnS + j*8 + c*2;
                int grow0 = qt*FBM + rl0, gcol0 = kb*FBN + cl0;
                float* t = sacc[i*4+j];
                sS[rl0*SSTR + cl0]       = (gcol0   <= grow0  ) ? t[0]*scale : -1e30f;
                sS[rl0*SSTR + cl0+1]     = (gcol0+1 <= grow0  ) ? t[1]*scale : -1e30f;
                sS[(rl0+8)*SSTR + cl0]   = (gcol0   <= grow0+8) ? t[2]*scale : -1e30f;
                sS[(rl0+8)*SSTR + cl0+1] = (gcol0+1 <= grow0+8) ? t[3]*scale : -1e30f;
            }
        }
        __syncthreads();

        // ---- online softmax: 2 threads per row ----
        {
            int row = tid >> 1, part = tid & 1;
            float mo = sMx[row];
            float mx = mo;
            #pragma unroll
            for (int jj = 0; jj < 32; jj++)
                mx = fmaxf(mx, sS[row*SSTR + part*32 + jj]);
            mx = fmaxf(mx, __shfl_xor_sync(0xffffffffu, mx, 1));
            float sum = 0.f;
            #pragma unroll
            for (int jj = 0; jj < 32; jj++) {
                float p = to_tf32(__expf(sS[row*SSTR + part*32 + jj] - mx));
                sS[row*SSTR + part*32 + jj] = p;
                sum += p;
            }
            sum += __shfl_xor_sync(0xffffffffu, sum, 1);
            if (part == 0) {
                float al = __expf(mo - mx);
                sL[row] = sL[row]*al + sum;
                sMx[row] = mx;
                sA[row] = al;
            }
        }
        __syncthreads();

        // ---- O = O*alpha + P V : warp tile 32x64 (2 m-tiles x 8 n-tiles) ----
        #pragma unroll
        for (int i = 0; i < 2; i++) {
            float al0 = sA[wm + i*16 + r];
            float al1 = sA[wm + i*16 + r + 8];
            #pragma unroll
            for (int j = 0; j < 8; j++) {
                oacc[i*8+j][0] *= al0; oacc[i*8+j][1] *= al0;
                oacc[i*8+j][2] *= al1; oacc[i*8+j][3] *= al1;
            }
        }
        #pragma unroll
        for (int s = 0; s < 8; s++) {
            int kc = s * 8;
            uint32_t af[2][4], bf[8][2];
            #pragma unroll
            for (int i = 0; i < 2; i++) {
                int m0 = wm + i*16 + r;
                af[i][0] = __float_as_uint(sS[m0*SSTR      + kc+c]);
                af[i][1] = __float_as_uint(sS[(m0+8)*SSTR  + kc+c]);
                af[i][2] = __float_as_uint(sS[m0*SSTR      + kc+c+4]);
                af[i][3] = __float_as_uint(sS[(m0+8)*SSTR  + kc+c+4]);
            }
            int vr0 = (kc + c) * DH, vr1 = (kc + c + 4) * DH;
            #pragma unroll
            for (int j = 0; j < 8; j++) {
                bf[j][0] = __float_as_uint(Vb[vr0 + vcol0[j]]);
                bf[j][1] = __float_as_uint(Vb[vr1 + vcol1[j]]);
            }
            #pragma unroll
            for (int i = 0; i < 2; i++)
                #pragma unroll
                for (int j = 0; j < 8; j++)
                    mma_tf32(oacc[i*8+j], af[i][0],af[i][1],af[i][2],af[i][3],
                             bf[j][0], bf[j][1]);
        }
    }
    __syncthreads();

    // epilogue: O /= L, tf32-round (feeds WO GEMM), write
    #pragma unroll
    for (int i = 0; i < 2; i++) {
        int rl0 = wm + i*16 + r;
        float inv0 = 1.0f / sL[rl0];
        float inv1 = 1.0f / sL[rl0 + 8];
        int q0 = qt*FBM + rl0;
        #pragma unroll
        for (int j = 0; j < 8; j++) {
            int col = wnO + j*8 + c*2;
            float2 v0, v1;
            v0.x = to_tf32(oacc[i*8+j][0]*inv0); v0.y = to_tf32(oacc[i*8+j][1]*inv0);
            v1.x = to_tf32(oacc[i*8+j][2]*inv1); v1.y = to_tf32(oacc[i*8+j][3]*inv1);
            *(float2*)&g_attn[((size_t)(b*QLEN + q0  ))*(HQ*DH) + h*DH + col] = v0;
            *(float2*)&g_attn[((size_t)(b*QLEN + q0+8))*(HQ*DH) + h*DH + col] = v1;
        }
    }
}

// ---------------------------------------------------------------------------
extern "C" void kernel_launch(void* const* d_in, const int* in_sizes, int n_in,
                              void* d_out, int out_size)
{
    const int*   positions = (const int*)  d_in[0];
    const float* hidden    = (const float*)d_in[1];
    const float* wqkv      = (const float*)d_in[4];
    const float* wo        = (const float*)d_in[5];
    const float* qw        = (const float*)d_in[6];
    const float* kw        = (const float*)d_in[7];
    float* out = (float*)d_out;

    float *p_qkv, *p_attn, *p_hidr, *p_wqkvr, *p_wor;
    cudaGetSymbolAddress((void**)&p_qkv,   g_qkv);
    cudaGetSymbolAddress((void**)&p_attn,  g_attn);
    cudaGetSymbolAddress((void**)&p_hidr,  g_hidr);
    cudaGetSymbolAddress((void**)&p_wqkvr, g_wqkvr);
    cudaGetSymbolAddress((void**)&p_wor,   g_wor);

    cudaFuncSetAttribute(gemm_tf32,  cudaFuncAttributeMaxDynamicSharedMemorySize, GEMM_SMEM);
    cudaFuncSetAttribute(flash_attn, cudaFuncAttributeMaxDynamicSharedMemorySize, FLASH_SMEM);

    // 0) tf32 rounding prepass (RNA)
    round_tf32_vec<<<(NTOK*HID/4 + 255)/256, 256>>>(hidden, p_hidr, NTOK*HID/4);
    round_tf32_vec<<<(QKVN*HID/4 + 255)/256, 256>>>(wqkv, p_wqkvr, QKVN*HID/4);
    round_tf32_vec<<<(HID*HID/4 + 255)/256, 256>>>(wo, p_wor, HID*HID/4);

    // 1) QKV projection
    gemm_tf32<<<dim3(QKVN/128, NTOK/128), 256, GEMM_SMEM>>>(p_hidr, p_wqkvr, p_qkv, NTOK, QKVN, HID);

    // 2) RMSNorm + RoPE + scatter
    rmsnorm_rope<<<dim3(NTOK, 24), 128>>>(positions, qw, kw);

    // 3) causal GQA flash attention (Q tile 128, longest-first)
    flash_attn<<<dim3(QLEN/FBM, HQ, B_), 256, FLASH_SMEM>>>();

    // 4) output projection
    gemm_tf32<<<dim3(HID/128, NTOK/128), 256, GEMM_SMEM>>>(p_attn, p_wor, out, NTOK, HID, HID);
}